// round 10
// baseline (speedup 1.0000x reference)
#include <cuda_runtime.h>
#include <cstdint>
#include <cstddef>

#define Hd 128
#define FEAT 512
#define NSRC0 50000
#define NDST0 20000
#define NDST1 4096
#define E0 320000
#define E1 65536

#define OFF_S0 0
#define OFF_D0 (NSRC0)
#define OFF_S1 (NSRC0 + NDST0)
#define OFF_D1 (NSRC0 + 2 * NDST0)
#define CNT_TOTAL (NSRC0 + 2 * NDST0 + NDST1)

// layer-0 pipeline chunking
#define CH0 4000          // nodes per chunk (divisible by 32)
#define NCH0 5
#define CH1 2048
#define NCH1 2

// ---------------- scratch (device globals; no allocations) ----------------
__device__ float g_X[(size_t)NSRC0 * FEAT];
__device__ float g_agg0[(size_t)NDST0 * FEAT];
__device__ float g_h0[(size_t)NDST0 * FEAT];
__device__ float g_agg1[(size_t)NDST1 * FEAT];

__device__ int g_cnt[CNT_TOTAL];
__device__ float g_ns0[NSRC0];
__device__ float g_nd0[NDST0];
__device__ float g_ns1[NDST0];
__device__ float g_nd1[NDST1];

__device__ int g_off0[NDST0 + 1];
__device__ int g_cur0[NDST0];
__device__ int g_csr0[E0];
__device__ int g_off1[NDST1 + 1];
__device__ int g_cur1[NDST1];
__device__ int g_csr1[E1];

// ---------------- degree histogram (counts zeroed by memsetAsync) ----------------
__global__ void k_hist(const int* __restrict__ s0, const int* __restrict__ d0,
                       const int* __restrict__ s1, const int* __restrict__ d1) {
    int i = blockIdx.x * blockDim.x + threadIdx.x;
    if (i < E0) {
        atomicAdd(&g_cnt[OFF_S0 + s0[i]], 1);
        atomicAdd(&g_cnt[OFF_D0 + d0[i]], 1);
    }
    if (i < E1) {
        atomicAdd(&g_cnt[OFF_S1 + s1[i]], 1);
        atomicAdd(&g_cnt[OFF_D1 + d1[i]], 1);
    }
}

// ---------------- scan (blocks 0,1) + norms (blocks 2+) ----------------
__global__ void __launch_bounds__(1024) k_prep() {
    int bid = blockIdx.x;
    if (bid < 2) {
        const int* cnt; int* off; int* cur; int n;
        if (bid == 0) { cnt = g_cnt + OFF_D0; off = g_off0; cur = g_cur0; n = NDST0; }
        else          { cnt = g_cnt + OFF_D1; off = g_off1; cur = g_cur1; n = NDST1; }
        int t = threadIdx.x;
        int per = (n + 1023) >> 10;
        int base = t * per;
        int s = 0;
        for (int i = 0; i < per; i++)
            if (base + i < n) s += cnt[base + i];
        int lane = t & 31, wid = t >> 5;
        int v = s;
        #pragma unroll
        for (int d = 1; d < 32; d <<= 1) {
            int x = __shfl_up_sync(~0u, v, d);
            if (lane >= d) v += x;
        }
        __shared__ int wsum[32];
        if (lane == 31) wsum[wid] = v;
        __syncthreads();
        if (wid == 0) {
            int wv = wsum[lane];
            #pragma unroll
            for (int d = 1; d < 32; d <<= 1) {
                int x = __shfl_up_sync(~0u, wv, d);
                if (lane >= d) wv += x;
            }
            wsum[lane] = wv;
        }
        __syncthreads();
        int run = v - s + (wid ? wsum[wid - 1] : 0);
        for (int i = 0; i < per; i++) {
            int idx = base + i;
            if (idx < n) { off[idx] = run; cur[idx] = run; run += cnt[idx]; }
        }
        if (t == 1023) off[n] = run;
    } else {
        int i = (bid - 2) * 1024 + threadIdx.x;
        if (i < NSRC0) g_ns0[i] = rsqrtf((float)max(g_cnt[OFF_S0 + i], 1));
        if (i < NDST0) {
            g_nd0[i] = rsqrtf((float)max(g_cnt[OFF_D0 + i], 1));
            g_ns1[i] = rsqrtf((float)max(g_cnt[OFF_S1 + i], 1));
        }
        if (i < NDST1) g_nd1[i] = rsqrtf((float)max(g_cnt[OFF_D1 + i], 1));
    }
}

__global__ void k_fill(const int* __restrict__ s0, const int* __restrict__ d0,
                       const int* __restrict__ s1, const int* __restrict__ d1) {
    int i = blockIdx.x * blockDim.x + threadIdx.x;
    if (i < E0) { int p = atomicAdd(&g_cur0[d0[i]], 1); g_csr0[p] = s0[i]; }
    if (i < E1) { int p = atomicAdd(&g_cur1[d1[i]], 1); g_csr1[p] = s1[i]; }
}

// ---------------- vectorized input transpose (swizzled smem) ----------------
__global__ void __launch_bounds__(256) k_transpose(const float* __restrict__ inf) {
    __shared__ float4 sm4[64 * 33];
    const float* sm = (const float*)sm4;
    int fi0 = blockIdx.y * 64;
    int n0  = blockIdx.x * 128;
    int tid = threadIdx.x;

    #pragma unroll
    for (int i = 0; i < 8; i++) {
        int idx = i * 256 + tid;
        int f = idx >> 5;
        int v = idx & 31;
        int n = n0 + v * 4;
        if (n < NSRC0) {
            float4 x = *(const float4*)(inf + (size_t)(fi0 + f) * NSRC0 + n);
            sm4[f * 33 + (v ^ (f >> 3))] = x;
        }
    }
    __syncthreads();

    int a  = fi0 >> 8;
    int h0 = (fi0 & 255) >> 1;
    #pragma unroll
    for (int i = 0; i < 8; i++) {
        int idx = i * 256 + tid;
        int ln = idx >> 4;
        int rest = idx & 15;
        int c = rest >> 3;
        int q = rest & 7;
        int n = n0 + ln;
        if (n < NSRC0) {
            int col = (ln >> 2) ^ q;
            int el  = ln & 3;
            float4 o;
            o.x = sm[((8 * q + 0 + c) * 33 + col) * 4 + el];
            o.y = sm[((8 * q + 2 + c) * 33 + col) * 4 + el];
            o.z = sm[((8 * q + 4 + c) * 33 + col) * 4 + el];
            o.w = sm[((8 * q + 6 + c) * 33 + col) * 4 + el];
            *(float4*)(g_X + (size_t)n * FEAT + a * 256 + c * 128 + h0 + q * 4) = o;
        }
    }
}

// ---------------- aggregation: warp per dst, chunked via node_base ----------------
__global__ void k_agg(const int* __restrict__ off, const int* __restrict__ csr,
                      const float* __restrict__ feat, const float* __restrict__ ns,
                      float* __restrict__ out, int node_base, int node_end) {
    int w = node_base + ((blockIdx.x * blockDim.x + threadIdx.x) >> 5);
    int lane = threadIdx.x & 31;
    if (w >= node_end) return;
    int beg = off[w], end = off[w + 1];
    float4 a0 = make_float4(0.f, 0.f, 0.f, 0.f), a1 = a0, a2 = a0, a3 = a0;
    int e = beg;
    for (; e + 1 < end; e += 2) {
        int sA = csr[e], sB = csr[e + 1];
        float wA = ns ? ns[sA] : 1.f;
        float wB = ns ? ns[sB] : 1.f;
        const float4* pA = (const float4*)(feat + (size_t)sA * FEAT) + lane;
        const float4* pB = (const float4*)(feat + (size_t)sB * FEAT) + lane;
        float4 v0 = pA[0], v1 = pA[32], v2 = pA[64], v3 = pA[96];
        float4 u0 = pB[0], u1 = pB[32], u2 = pB[64], u3 = pB[96];
        a0.x += wA * v0.x + wB * u0.x; a0.y += wA * v0.y + wB * u0.y;
        a0.z += wA * v0.z + wB * u0.z; a0.w += wA * v0.w + wB * u0.w;
        a1.x += wA * v1.x + wB * u1.x; a1.y += wA * v1.y + wB * u1.y;
        a1.z += wA * v1.z + wB * u1.z; a1.w += wA * v1.w + wB * u1.w;
        a2.x += wA * v2.x + wB * u2.x; a2.y += wA * v2.y + wB * u2.y;
        a2.z += wA * v2.z + wB * u2.z; a2.w += wA * v2.w + wB * u2.w;
        a3.x += wA * v3.x + wB * u3.x; a3.y += wA * v3.y + wB * u3.y;
        a3.z += wA * v3.z + wB * u3.z; a3.w += wA * v3.w + wB * u3.w;
    }
    if (e < end) {
        int sA = csr[e];
        float wA = ns ? ns[sA] : 1.f;
        const float4* pA = (const float4*)(feat + (size_t)sA * FEAT) + lane;
        float4 v0 = pA[0], v1 = pA[32], v2 = pA[64], v3 = pA[96];
        a0.x += wA * v0.x; a0.y += wA * v0.y; a0.z += wA * v0.z; a0.w += wA * v0.w;
        a1.x += wA * v1.x; a1.y += wA * v1.y; a1.z += wA * v1.z; a1.w += wA * v1.w;
        a2.x += wA * v2.x; a2.y += wA * v2.y; a2.z += wA * v2.z; a2.w += wA * v2.w;
        a3.x += wA * v3.x; a3.y += wA * v3.y; a3.z += wA * v3.z; a3.w += wA * v3.w;
    }
    float4* o = (float4*)(out + (size_t)w * FEAT) + lane;
    o[0] = a0; o[32] = a1; o[64] = a2; o[96] = a3;
}

// ---------------- GEMM: 128-row blocks, chunked via node_base ----------------
#define SA 132
__global__ void __launch_bounds__(256, 1)
k_gemm(const float* __restrict__ A, const float* __restrict__ Wm,
       const float* __restrict__ bias, const float* __restrict__ nd,
       const float* __restrict__ s2, float* __restrict__ Crow, float* __restrict__ Ctr,
       int node_base) {
    extern __shared__ float sh[];
    float* Ash = sh;                 // [128][SA]
    float* Ws  = sh + 128 * SA;      // [128][SA]
    float* bs  = sh + 2 * 128 * SA;  // [128]
    int tid = threadIdx.x;
    int node0 = node_base + blockIdx.x * 32;
    size_t row0 = (size_t)node0 * 4;

    #pragma unroll 4
    for (int i = tid; i < 4096; i += 256) {
        int r = i >> 5, k4 = i & 31;
        float4 v = *((const float4*)(A + (row0 + r) * Hd) + k4);
        *(float4*)(Ash + r * SA + k4 * 4) = v;
    }
    #pragma unroll 4
    for (int i = tid; i < 4096; i += 256) {
        int k = i >> 5, c4 = i & 31;
        *(float4*)(Ws + k * SA + c4 * 4) = *((const float4*)(Wm + k * Hd) + c4);
    }
    if (tid < 128) bs[tid] = bias[tid];
    __syncthreads();

    int rowgrp = tid >> 3;
    int colgrp = tid & 7;

    unsigned long long acc[4][8];
    #pragma unroll
    for (int i = 0; i < 4; i++)
        #pragma unroll
        for (int j = 0; j < 8; j++) acc[i][j] = 0ull;

    #pragma unroll 4
    for (int k = 0; k < 128; k++) {
        unsigned long long ap[4];
        #pragma unroll
        for (int i = 0; i < 4; i++) {
            float av = Ash[(rowgrp * 4 + i) * SA + k];
            asm("mov.b64 %0, {%1, %1};" : "=l"(ap[i]) : "f"(av));
        }
        ulonglong2 wv[4];
        #pragma unroll
        for (int j = 0; j < 4; j++)
            wv[j] = *(const ulonglong2*)(Ws + k * SA + (j * 8 + colgrp) * 4);
        #pragma unroll
        for (int i = 0; i < 4; i++) {
            #pragma unroll
            for (int j = 0; j < 4; j++) {
                asm("fma.rn.f32x2 %0, %1, %2, %0;" : "+l"(acc[i][2 * j])     : "l"(ap[i]), "l"(wv[j].x));
                asm("fma.rn.f32x2 %0, %1, %2, %0;" : "+l"(acc[i][2 * j + 1]) : "l"(ap[i]), "l"(wv[j].y));
            }
        }
    }

    if (Ctr == nullptr) {
        #pragma unroll
        for (int i = 0; i < 4; i++) {
            int r = rowgrp * 4 + i;
            int node = node0 + (r >> 2);
            float scale = nd[node];
            float s2v = s2 ? s2[node] : 1.f;
            size_t grow = row0 + r;
            #pragma unroll
            for (int j = 0; j < 4; j++) {
                int c4 = j * 8 + colgrp;
                float4 o;
                asm("mov.b64 {%0, %1}, %2;" : "=f"(o.x), "=f"(o.y) : "l"(acc[i][2 * j]));
                asm("mov.b64 {%0, %1}, %2;" : "=f"(o.z), "=f"(o.w) : "l"(acc[i][2 * j + 1]));
                float4 bb = *(const float4*)(bs + c4 * 4);
                o.x = fmaxf(o.x * scale + bb.x, 0.f) * s2v;
                o.y = fmaxf(o.y * scale + bb.y, 0.f) * s2v;
                o.z = fmaxf(o.z * scale + bb.z, 0.f) * s2v;
                o.w = fmaxf(o.w * scale + bb.w, 0.f) * s2v;
                *(float4*)(Crow + grow * Hd + c4 * 4) = o;
            }
        }
    } else {
        __syncthreads();
        float* Fsh = Ash;                // reuse as [512][33]
        #pragma unroll
        for (int i = 0; i < 4; i++) {
            int r = rowgrp * 4 + i;
            int ln = r >> 2, g = r & 3;
            int node = node0 + ln;
            float scale = nd[node];
            #pragma unroll
            for (int j = 0; j < 4; j++) {
                int c4 = j * 8 + colgrp;
                float4 o;
                asm("mov.b64 {%0, %1}, %2;" : "=f"(o.x), "=f"(o.y) : "l"(acc[i][2 * j]));
                asm("mov.b64 {%0, %1}, %2;" : "=f"(o.z), "=f"(o.w) : "l"(acc[i][2 * j + 1]));
                float4 bb = *(const float4*)(bs + c4 * 4);
                int fb = g * 128 + c4 * 4;
                Fsh[(fb + 0) * 33 + ln] = fmaxf(o.x * scale + bb.x, 0.f);
                Fsh[(fb + 1) * 33 + ln] = fmaxf(o.y * scale + bb.y, 0.f);
                Fsh[(fb + 2) * 33 + ln] = fmaxf(o.z * scale + bb.z, 0.f);
                Fsh[(fb + 3) * 33 + ln] = fmaxf(o.w * scale + bb.w, 0.f);
            }
        }
        __syncthreads();
        int lane = tid & 31;
        for (int f = tid >> 5; f < FEAT; f += 8) {
            int g = f >> 7, h = f & 127;
            int a = g >> 1, c = g & 1;
            int fo = (a * 128 + h) * 2 + c;
            Ctr[(size_t)fo * NDST1 + node0 + lane] = Fsh[f * 33 + lane];
        }
    }
}

// ---------------- launcher: chunked agg/gemm pipeline across 2 streams ----------------
extern "C" void kernel_launch(void* const* d_in, const int* in_sizes, int n_in,
                              void* d_out, int out_size) {
    const float* in_feat = (const float*)d_in[0];
    const float* W       = (const float*)d_in[1];
    const float* b       = (const float*)d_in[2];
    const int* e0s = (const int*)d_in[3];
    const int* e0d = (const int*)d_in[4];
    const int* e1s = (const int*)d_in[5];
    const int* e1d = (const int*)d_in[6];
    float* out = (float*)d_out;

    void *pX, *pagg0, *ph0, *pagg1, *pcnt;
    void *poff0, *pcsr0, *poff1, *pcsr1;
    void *pns0, *pnd0, *pns1, *pnd1;
    cudaGetSymbolAddress(&pX, g_X);
    cudaGetSymbolAddress(&pagg0, g_agg0);
    cudaGetSymbolAddress(&ph0, g_h0);
    cudaGetSymbolAddress(&pagg1, g_agg1);
    cudaGetSymbolAddress(&pcnt, g_cnt);
    cudaGetSymbolAddress(&poff0, g_off0);
    cudaGetSymbolAddress(&pcsr0, g_csr0);
    cudaGetSymbolAddress(&poff1, g_off1);
    cudaGetSymbolAddress(&pcsr1, g_csr1);
    cudaGetSymbolAddress(&pns0, g_ns0);
    cudaGetSymbolAddress(&pnd0, g_nd0);
    cudaGetSymbolAddress(&pns1, g_ns1);
    cudaGetSymbolAddress(&pnd1, g_nd1);

    int smem_bytes = (2 * 128 * SA + 128) * (int)sizeof(float);
    cudaFuncSetAttribute(k_gemm, cudaFuncAttributeMaxDynamicSharedMemorySize, smem_bytes);

    // streams + events (created once; no device memory)
    static cudaStream_t s2 = nullptr, s3 = nullptr;
    static cudaEvent_t evFork = nullptr, evT = nullptr, evG0 = nullptr, evEnd = nullptr;
    static cudaEvent_t evA0[NCH0], evA1[NCH1];
    if (!s2) {
        cudaStreamCreateWithFlags(&s2, cudaStreamNonBlocking);
        cudaStreamCreateWithFlags(&s3, cudaStreamNonBlocking);
        cudaEventCreateWithFlags(&evFork, cudaEventDisableTiming);
        cudaEventCreateWithFlags(&evT, cudaEventDisableTiming);
        cudaEventCreateWithFlags(&evG0, cudaEventDisableTiming);
        cudaEventCreateWithFlags(&evEnd, cudaEventDisableTiming);
        for (int i = 0; i < NCH0; i++) cudaEventCreateWithFlags(&evA0[i], cudaEventDisableTiming);
        for (int i = 0; i < NCH1; i++) cudaEventCreateWithFlags(&evA1[i], cudaEventDisableTiming);
    }

    // fork: transpose on s2 (depends only on in_feat)
    cudaEventRecord(evFork, 0);
    cudaStreamWaitEvent(s2, evFork, 0);
    {
        dim3 gr((NSRC0 + 127) / 128, FEAT / 64);
        k_transpose<<<gr, 256, 0, s2>>>(in_feat);
    }
    cudaEventRecord(evT, s2);
    cudaStreamWaitEvent(s3, evFork, 0);   // s3 joins the party (for gemm chunks)

    // main stream: graph prep chain
    cudaMemsetAsync(pcnt, 0, CNT_TOTAL * sizeof(int));
    k_hist<<<(E0 + 255) / 256, 256>>>(e0s, e0d, e1s, e1d);
    k_prep<<<2 + (NSRC0 + 1023) / 1024, 1024>>>();
    k_fill<<<(E0 + 255) / 256, 256>>>(e0s, e0d, e1s, e1d);

    // transpose must be done before aggregation
    cudaStreamWaitEvent(0, evT, 0);

    // layer 0 pipeline: agg chunks on stream 0, gemm chunks on s3
    for (int c = 0; c < NCH0; c++) {
        int nb = c * CH0;
        k_agg<<<CH0 * 32 / 256, 256>>>((const int*)poff0, (const int*)pcsr0,
                                       (const float*)pX, (const float*)pns0,
                                       (float*)pagg0, nb, nb + CH0);
        cudaEventRecord(evA0[c], 0);
        cudaStreamWaitEvent(s3, evA0[c], 0);
        k_gemm<<<CH0 / 32, 256, smem_bytes, s3>>>((const float*)pagg0, W, b,
                                                  (const float*)pnd0, (const float*)pns1,
                                                  (float*)ph0, nullptr, nb);
    }
    cudaEventRecord(evG0, s3);
    cudaStreamWaitEvent(0, evG0, 0);   // h0 complete before agg1

    // layer 1 pipeline
    for (int c = 0; c < NCH1; c++) {
        int nb = c * CH1;
        k_agg<<<CH1 * 32 / 256, 256>>>((const int*)poff1, (const int*)pcsr1,
                                       (const float*)ph0, (const float*)nullptr,
                                       (float*)pagg1, nb, nb + CH1);
        cudaEventRecord(evA1[c], 0);
        cudaStreamWaitEvent(s3, evA1[c], 0);
        k_gemm<<<CH1 / 32, 256, smem_bytes, s3>>>((const float*)pagg1, W, b,
                                                  (const float*)pnd1, (const float*)nullptr,
                                                  nullptr, out, nb);
    }
    cudaEventRecord(evEnd, s3);
    cudaStreamWaitEvent(0, evEnd, 0);   // rejoin origin stream before capture end

    (void)in_sizes; (void)n_in; (void)out_size;
}

// round 13
// speedup vs baseline: 1.1274x; 1.1274x over previous
#include <cuda_runtime.h>
#include <cstdint>
#include <cstddef>

#define Hd 128
#define FEAT 512
#define NSRC0 50000
#define NDST0 20000
#define NDST1 4096
#define E0 320000
#define E1 65536

#define OFF_S0 0
#define OFF_D0 (NSRC0)
#define OFF_S1 (NSRC0 + NDST0)
#define OFF_D1 (NSRC0 + 2 * NDST0)
#define CNT_TOTAL (NSRC0 + 2 * NDST0 + NDST1)

// ---------------- scratch (device globals; no allocations) ----------------
__device__ float g_X[(size_t)NSRC0 * FEAT];
__device__ float g_agg0[(size_t)NDST0 * FEAT];
__device__ float g_h0[(size_t)NDST0 * FEAT];
__device__ float g_agg1[(size_t)NDST1 * FEAT];

__device__ int g_cnt[CNT_TOTAL];
__device__ float g_ns0[NSRC0];
__device__ float g_nd0[NDST0];
__device__ float g_ns1[NDST0];
__device__ float g_nd1[NDST1];

__device__ int g_off0[NDST0 + 1];
__device__ int g_cur0[NDST0];
__device__ int g_csr0[E0];
__device__ int g_off1[NDST1 + 1];
__device__ int g_cur1[NDST1];
__device__ int g_csr1[E1];

// ---------------- degree histogram (counts zeroed by memsetAsync) ----------------
__global__ void k_hist(const int* __restrict__ s0, const int* __restrict__ d0,
                       const int* __restrict__ s1, const int* __restrict__ d1) {
    int i = blockIdx.x * blockDim.x + threadIdx.x;
    if (i < E0) {
        atomicAdd(&g_cnt[OFF_S0 + s0[i]], 1);
        atomicAdd(&g_cnt[OFF_D0 + d0[i]], 1);
    }
    if (i < E1) {
        atomicAdd(&g_cnt[OFF_S1 + s1[i]], 1);
        atomicAdd(&g_cnt[OFF_D1 + d1[i]], 1);
    }
}

// ---------------- scan (blocks 0,1) + norms (blocks 2+) ----------------
__global__ void __launch_bounds__(1024) k_prep() {
    int bid = blockIdx.x;
    if (bid < 2) {
        const int* cnt; int* off; int* cur; int n;
        if (bid == 0) { cnt = g_cnt + OFF_D0; off = g_off0; cur = g_cur0; n = NDST0; }
        else          { cnt = g_cnt + OFF_D1; off = g_off1; cur = g_cur1; n = NDST1; }
        int t = threadIdx.x;
        int per = (n + 1023) >> 10;
        int base = t * per;
        int s = 0;
        for (int i = 0; i < per; i++)
            if (base + i < n) s += cnt[base + i];
        int lane = t & 31, wid = t >> 5;
        int v = s;
        #pragma unroll
        for (int d = 1; d < 32; d <<= 1) {
            int x = __shfl_up_sync(~0u, v, d);
            if (lane >= d) v += x;
        }
        __shared__ int wsum[32];
        if (lane == 31) wsum[wid] = v;
        __syncthreads();
        if (wid == 0) {
            int wv = wsum[lane];
            #pragma unroll
            for (int d = 1; d < 32; d <<= 1) {
                int x = __shfl_up_sync(~0u, wv, d);
                if (lane >= d) wv += x;
            }
            wsum[lane] = wv;
        }
        __syncthreads();
        int run = v - s + (wid ? wsum[wid - 1] : 0);
        for (int i = 0; i < per; i++) {
            int idx = base + i;
            if (idx < n) { off[idx] = run; cur[idx] = run; run += cnt[idx]; }
        }
        if (t == 1023) off[n] = run;
    } else {
        int i = (bid - 2) * 1024 + threadIdx.x;
        if (i < NSRC0) g_ns0[i] = rsqrtf((float)max(g_cnt[OFF_S0 + i], 1));
        if (i < NDST0) {
            g_nd0[i] = rsqrtf((float)max(g_cnt[OFF_D0 + i], 1));
            g_ns1[i] = rsqrtf((float)max(g_cnt[OFF_S1 + i], 1));
        }
        if (i < NDST1) g_nd1[i] = rsqrtf((float)max(g_cnt[OFF_D1 + i], 1));
    }
}

__global__ void k_fill(const int* __restrict__ s0, const int* __restrict__ d0,
                       const int* __restrict__ s1, const int* __restrict__ d1) {
    int i = blockIdx.x * blockDim.x + threadIdx.x;
    if (i < E0) { int p = atomicAdd(&g_cur0[d0[i]], 1); g_csr0[p] = s0[i]; }
    if (i < E1) { int p = atomicAdd(&g_cur1[d1[i]], 1); g_csr1[p] = s1[i]; }
}

// ---------------- vectorized input transpose (swizzled smem) ----------------
__global__ void __launch_bounds__(256) k_transpose(const float* __restrict__ inf) {
    __shared__ float4 sm4[64 * 33];
    const float* sm = (const float*)sm4;
    int fi0 = blockIdx.y * 64;
    int n0  = blockIdx.x * 128;
    int tid = threadIdx.x;

    #pragma unroll
    for (int i = 0; i < 8; i++) {
        int idx = i * 256 + tid;
        int f = idx >> 5;
        int v = idx & 31;
        int n = n0 + v * 4;
        if (n < NSRC0) {
            float4 x = *(const float4*)(inf + (size_t)(fi0 + f) * NSRC0 + n);
            sm4[f * 33 + (v ^ (f >> 3))] = x;
        }
    }
    __syncthreads();

    int a  = fi0 >> 8;
    int h0 = (fi0 & 255) >> 1;
    #pragma unroll
    for (int i = 0; i < 8; i++) {
        int idx = i * 256 + tid;
        int ln = idx >> 4;
        int rest = idx & 15;
        int c = rest >> 3;
        int q = rest & 7;
        int n = n0 + ln;
        if (n < NSRC0) {
            int col = (ln >> 2) ^ q;
            int el  = ln & 3;
            float4 o;
            o.x = sm[((8 * q + 0 + c) * 33 + col) * 4 + el];
            o.y = sm[((8 * q + 2 + c) * 33 + col) * 4 + el];
            o.z = sm[((8 * q + 4 + c) * 33 + col) * 4 + el];
            o.w = sm[((8 * q + 6 + c) * 33 + col) * 4 + el];
            *(float4*)(g_X + (size_t)n * FEAT + a * 256 + c * 128 + h0 + q * 4) = o;
        }
    }
}

// ---------------- aggregation: 2 warps per dst (feature-split), 256 feats/warp ----------------
__global__ void k_agg(const int* __restrict__ off, const int* __restrict__ csr,
                      const float* __restrict__ feat, const float* __restrict__ ns,
                      float* __restrict__ out, int ndst) {
    int gw = (blockIdx.x * blockDim.x + threadIdx.x) >> 5;
    int node = gw >> 1;
    int half = gw & 1;
    int lane = threadIdx.x & 31;
    if (node >= ndst) return;
    int beg = off[node], end = off[node + 1];
    const float4* base = (const float4*)feat + half * 64 + lane;
    float4 a0 = make_float4(0.f, 0.f, 0.f, 0.f), a1 = a0;
    int e = beg;
    for (; e + 1 < end; e += 2) {
        int sA = csr[e], sB = csr[e + 1];
        float wA = ns ? ns[sA] : 1.f;
        float wB = ns ? ns[sB] : 1.f;
        const float4* pA = base + (size_t)sA * 128;
        const float4* pB = base + (size_t)sB * 128;
        float4 v0 = pA[0], v1 = pA[32];
        float4 u0 = pB[0], u1 = pB[32];
        a0.x += wA * v0.x + wB * u0.x; a0.y += wA * v0.y + wB * u0.y;
        a0.z += wA * v0.z + wB * u0.z; a0.w += wA * v0.w + wB * u0.w;
        a1.x += wA * v1.x + wB * u1.x; a1.y += wA * v1.y + wB * u1.y;
        a1.z += wA * v1.z + wB * u1.z; a1.w += wA * v1.w + wB * u1.w;
    }
    if (e < end) {
        int sA = csr[e];
        float wA = ns ? ns[sA] : 1.f;
        const float4* pA = base + (size_t)sA * 128;
        float4 v0 = pA[0], v1 = pA[32];
        a0.x += wA * v0.x; a0.y += wA * v0.y; a0.z += wA * v0.z; a0.w += wA * v0.w;
        a1.x += wA * v1.x; a1.y += wA * v1.y; a1.z += wA * v1.z; a1.w += wA * v1.w;
    }
    float4* o = (float4*)out + (size_t)node * 128 + half * 64 + lane;
    o[0] = a0; o[32] = a1;
}

// ---------------- GEMM: 128-row blocks, 256 threads, 4x16 microtile, f32x2 FMA ----------------
#define SA 132
__global__ void __launch_bounds__(256, 1)
k_gemm(const float* __restrict__ A, const float* __restrict__ Wm,
       const float* __restrict__ bias, const float* __restrict__ nd,
       const float* __restrict__ s2, float* __restrict__ Crow, float* __restrict__ Ctr) {
    extern __shared__ float sh[];
    float* Ash = sh;                 // [128][SA]
    float* Ws  = sh + 128 * SA;      // [128][SA]
    float* bs  = sh + 2 * 128 * SA;  // [128]
    int tid = threadIdx.x;
    int node0 = blockIdx.x * 32;
    size_t row0 = (size_t)blockIdx.x * 128;

    #pragma unroll 4
    for (int i = tid; i < 4096; i += 256) {
        int r = i >> 5, k4 = i & 31;
        float4 v = *((const float4*)(A + (row0 + r) * Hd) + k4);
        *(float4*)(Ash + r * SA + k4 * 4) = v;
    }
    #pragma unroll 4
    for (int i = tid; i < 4096; i += 256) {
        int k = i >> 5, c4 = i & 31;
        *(float4*)(Ws + k * SA + c4 * 4) = *((const float4*)(Wm + k * Hd) + c4);
    }
    if (tid < 128) bs[tid] = bias[tid];
    __syncthreads();

    int rowgrp = tid >> 3;
    int colgrp = tid & 7;

    unsigned long long acc[4][8];
    #pragma unroll
    for (int i = 0; i < 4; i++)
        #pragma unroll
        for (int j = 0; j < 8; j++) acc[i][j] = 0ull;

    #pragma unroll 4
    for (int k = 0; k < 128; k++) {
        unsigned long long ap[4];
        #pragma unroll
        for (int i = 0; i < 4; i++) {
            float av = Ash[(rowgrp * 4 + i) * SA + k];
            asm("mov.b64 %0, {%1, %1};" : "=l"(ap[i]) : "f"(av));
        }
        ulonglong2 wv[4];
        #pragma unroll
        for (int j = 0; j < 4; j++)
            wv[j] = *(const ulonglong2*)(Ws + k * SA + (j * 8 + colgrp) * 4);
        #pragma unroll
        for (int i = 0; i < 4; i++) {
            #pragma unroll
            for (int j = 0; j < 4; j++) {
                asm("fma.rn.f32x2 %0, %1, %2, %0;" : "+l"(acc[i][2 * j])     : "l"(ap[i]), "l"(wv[j].x));
                asm("fma.rn.f32x2 %0, %1, %2, %0;" : "+l"(acc[i][2 * j + 1]) : "l"(ap[i]), "l"(wv[j].y));
            }
        }
    }

    if (Ctr == nullptr) {
        #pragma unroll
        for (int i = 0; i < 4; i++) {
            int r = rowgrp * 4 + i;
            int node = node0 + (r >> 2);
            float scale = nd[node];
            float s2v = s2 ? s2[node] : 1.f;
            size_t grow = row0 + r;
            #pragma unroll
            for (int j = 0; j < 4; j++) {
                int c4 = j * 8 + colgrp;
                float4 o;
                asm("mov.b64 {%0, %1}, %2;" : "=f"(o.x), "=f"(o.y) : "l"(acc[i][2 * j]));
                asm("mov.b64 {%0, %1}, %2;" : "=f"(o.z), "=f"(o.w) : "l"(acc[i][2 * j + 1]));
                float4 bb = *(const float4*)(bs + c4 * 4);
                o.x = fmaxf(o.x * scale + bb.x, 0.f) * s2v;
                o.y = fmaxf(o.y * scale + bb.y, 0.f) * s2v;
                o.z = fmaxf(o.z * scale + bb.z, 0.f) * s2v;
                o.w = fmaxf(o.w * scale + bb.w, 0.f) * s2v;
                *(float4*)(Crow + grow * Hd + c4 * 4) = o;
            }
        }
    } else {
        __syncthreads();
        float* Fsh = Ash;                // reuse as [512][33]
        #pragma unroll
        for (int i = 0; i < 4; i++) {
            int r = rowgrp * 4 + i;
            int ln = r >> 2, g = r & 3;
            int node = node0 + ln;
            float scale = nd[node];
            #pragma unroll
            for (int j = 0; j < 4; j++) {
                int c4 = j * 8 + colgrp;
                float4 o;
                asm("mov.b64 {%0, %1}, %2;" : "=f"(o.x), "=f"(o.y) : "l"(acc[i][2 * j]));
                asm("mov.b64 {%0, %1}, %2;" : "=f"(o.z), "=f"(o.w) : "l"(acc[i][2 * j + 1]));
                float4 bb = *(const float4*)(bs + c4 * 4);
                int fb = g * 128 + c4 * 4;
                Fsh[(fb + 0) * 33 + ln] = fmaxf(o.x * scale + bb.x, 0.f);
                Fsh[(fb + 1) * 33 + ln] = fmaxf(o.y * scale + bb.y, 0.f);
                Fsh[(fb + 2) * 33 + ln] = fmaxf(o.z * scale + bb.z, 0.f);
                Fsh[(fb + 3) * 33 + ln] = fmaxf(o.w * scale + bb.w, 0.f);
            }
        }
        __syncthreads();
        int lane = tid & 31;
        for (int f = tid >> 5; f < FEAT; f += 8) {
            int g = f >> 7, h = f & 127;
            int a = g >> 1, c = g & 1;
            int fo = (a * 128 + h) * 2 + c;
            Ctr[(size_t)fo * NDST1 + node0 + lane] = Fsh[f * 33 + lane];
        }
    }
}

// ---------------- launcher (prep chain || transpose; serial layers) ----------------
extern "C" void kernel_launch(void* const* d_in, const int* in_sizes, int n_in,
                              void* d_out, int out_size) {
    const float* in_feat = (const float*)d_in[0];
    const float* W       = (const float*)d_in[1];
    const float* b       = (const float*)d_in[2];
    const int* e0s = (const int*)d_in[3];
    const int* e0d = (const int*)d_in[4];
    const int* e1s = (const int*)d_in[5];
    const int* e1d = (const int*)d_in[6];
    float* out = (float*)d_out;

    void *pX, *pagg0, *ph0, *pagg1, *pcnt;
    void *poff0, *pcsr0, *poff1, *pcsr1;
    void *pns0, *pnd0, *pns1, *pnd1;
    cudaGetSymbolAddress(&pX, g_X);
    cudaGetSymbolAddress(&pagg0, g_agg0);
    cudaGetSymbolAddress(&ph0, g_h0);
    cudaGetSymbolAddress(&pagg1, g_agg1);
    cudaGetSymbolAddress(&pcnt, g_cnt);
    cudaGetSymbolAddress(&poff0, g_off0);
    cudaGetSymbolAddress(&pcsr0, g_csr0);
    cudaGetSymbolAddress(&poff1, g_off1);
    cudaGetSymbolAddress(&pcsr1, g_csr1);
    cudaGetSymbolAddress(&pns0, g_ns0);
    cudaGetSymbolAddress(&pnd0, g_nd0);
    cudaGetSymbolAddress(&pns1, g_ns1);
    cudaGetSymbolAddress(&pnd1, g_nd1);

    int smem_bytes = (2 * 128 * SA + 128) * (int)sizeof(float);
    cudaFuncSetAttribute(k_gemm, cudaFuncAttributeMaxDynamicSharedMemorySize, smem_bytes);

    static cudaStream_t s2 = nullptr;
    static cudaEvent_t evFork = nullptr, evT = nullptr;
    if (!s2) {
        cudaStreamCreateWithFlags(&s2, cudaStreamNonBlocking);
        cudaEventCreateWithFlags(&evFork, cudaEventDisableTiming);
        cudaEventCreateWithFlags(&evT, cudaEventDisableTiming);
    }

    // fork: transpose on s2 (depends only on in_feat; ns0 applied in agg0)
    cudaEventRecord(evFork, 0);
    cudaStreamWaitEvent(s2, evFork, 0);
    {
        dim3 gr((NSRC0 + 127) / 128, FEAT / 64);
        k_transpose<<<gr, 256, 0, s2>>>(in_feat);
    }
    cudaEventRecord(evT, s2);

    // main stream: graph prep chain
    cudaMemsetAsync(pcnt, 0, CNT_TOTAL * sizeof(int));
    k_hist<<<(E0 + 255) / 256, 256>>>(e0s, e0d, e1s, e1d);
    k_prep<<<2 + (NSRC0 + 1023) / 1024, 1024>>>();
    k_fill<<<(E0 + 255) / 256, 256>>>(e0s, e0d, e1s, e1d);

    cudaStreamWaitEvent(0, evT, 0);

    // layer 0: agg(*ns0[src], 2 warps/node) -> GEMM(*nd0 + b, relu, *ns1)
    k_agg<<<NDST0 / 4, 256>>>((const int*)poff0, (const int*)pcsr0,
                              (const float*)pX, (const float*)pns0,
                              (float*)pagg0, NDST0);
    k_gemm<<<NDST0 * 4 / 128, 256, smem_bytes>>>((const float*)pagg0, W, b,
                                                 (const float*)pnd0, (const float*)pns1,
                                                 (float*)ph0, nullptr);

    // layer 1: agg -> GEMM(*nd1 + b, relu) -> transposed out
    k_agg<<<NDST1 / 4, 256>>>((const int*)poff1, (const int*)pcsr1,
                              (const float*)ph0, (const float*)nullptr,
                              (float*)pagg1, NDST1);
    k_gemm<<<NDST1 * 4 / 128, 256, smem_bytes>>>((const float*)pagg1, W, b,
                                                 (const float*)pnd1, (const float*)nullptr,
                                                 nullptr, out);

    (void)in_sizes; (void)n_in; (void)out_size;
}

// round 14
// speedup vs baseline: 1.1304x; 1.0026x over previous
#include <cuda_runtime.h>
#include <cstdint>
#include <cstddef>

#define Hd 128
#define FEAT 512
#define NSRC0 50000
#define NDST0 20000
#define NDST1 4096
#define E0 320000
#define E1 65536

#define OFF_S0 0
#define OFF_D0 (NSRC0)
#define OFF_S1 (NSRC0 + NDST0)
#define OFF_D1 (NSRC0 + 2 * NDST0)
#define CNT_TOTAL (NSRC0 + 2 * NDST0 + NDST1)

// ---------------- scratch (device globals; no allocations) ----------------
__device__ float g_X[(size_t)NSRC0 * FEAT];
__device__ float g_agg0[(size_t)NDST0 * FEAT];
__device__ float g_h0[(size_t)NDST0 * FEAT];
__device__ float g_agg1[(size_t)NDST1 * FEAT];

__device__ int g_cnt[CNT_TOTAL];
__device__ float g_ns0[NSRC0];
__device__ float g_nd0[NDST0];
__device__ float g_ns1[NDST0];
__device__ float g_nd1[NDST1];

__device__ int g_off0[NDST0 + 1];
__device__ int g_cur0[NDST0];
__device__ int g_csr0[E0];
__device__ int g_off1[NDST1 + 1];
__device__ int g_cur1[NDST1];
__device__ int g_csr1[E1];

// ---------------- degree histogram (counts zeroed by memsetAsync) ----------------
__global__ void k_hist(const int* __restrict__ s0, const int* __restrict__ d0,
                       const int* __restrict__ s1, const int* __restrict__ d1) {
    int i = blockIdx.x * blockDim.x + threadIdx.x;
    if (i < E0) {
        atomicAdd(&g_cnt[OFF_S0 + s0[i]], 1);
        atomicAdd(&g_cnt[OFF_D0 + d0[i]], 1);
    }
    if (i < E1) {
        atomicAdd(&g_cnt[OFF_S1 + s1[i]], 1);
        atomicAdd(&g_cnt[OFF_D1 + d1[i]], 1);
    }
}

// ---------------- scan (blocks 0,1) + norms (blocks 2+) ----------------
__global__ void __launch_bounds__(1024) k_prep() {
    int bid = blockIdx.x;
    if (bid < 2) {
        const int* cnt; int* off; int* cur; int n;
        if (bid == 0) { cnt = g_cnt + OFF_D0; off = g_off0; cur = g_cur0; n = NDST0; }
        else          { cnt = g_cnt + OFF_D1; off = g_off1; cur = g_cur1; n = NDST1; }
        int t = threadIdx.x;
        int per = (n + 1023) >> 10;
        int base = t * per;
        int s = 0;
        for (int i = 0; i < per; i++)
            if (base + i < n) s += cnt[base + i];
        int lane = t & 31, wid = t >> 5;
        int v = s;
        #pragma unroll
        for (int d = 1; d < 32; d <<= 1) {
            int x = __shfl_up_sync(~0u, v, d);
            if (lane >= d) v += x;
        }
        __shared__ int wsum[32];
        if (lane == 31) wsum[wid] = v;
        __syncthreads();
        if (wid == 0) {
            int wv = wsum[lane];
            #pragma unroll
            for (int d = 1; d < 32; d <<= 1) {
                int x = __shfl_up_sync(~0u, wv, d);
                if (lane >= d) wv += x;
            }
            wsum[lane] = wv;
        }
        __syncthreads();
        int run = v - s + (wid ? wsum[wid - 1] : 0);
        for (int i = 0; i < per; i++) {
            int idx = base + i;
            if (idx < n) { off[idx] = run; cur[idx] = run; run += cnt[idx]; }
        }
        if (t == 1023) off[n] = run;
    } else {
        int i = (bid - 2) * 1024 + threadIdx.x;
        if (i < NSRC0) g_ns0[i] = rsqrtf((float)max(g_cnt[OFF_S0 + i], 1));
        if (i < NDST0) {
            g_nd0[i] = rsqrtf((float)max(g_cnt[OFF_D0 + i], 1));
            g_ns1[i] = rsqrtf((float)max(g_cnt[OFF_S1 + i], 1));
        }
        if (i < NDST1) g_nd1[i] = rsqrtf((float)max(g_cnt[OFF_D1 + i], 1));
    }
}

__global__ void k_fill(const int* __restrict__ s0, const int* __restrict__ d0,
                       const int* __restrict__ s1, const int* __restrict__ d1) {
    int i = blockIdx.x * blockDim.x + threadIdx.x;
    if (i < E0) { int p = atomicAdd(&g_cur0[d0[i]], 1); g_csr0[p] = s0[i]; }
    if (i < E1) { int p = atomicAdd(&g_cur1[d1[i]], 1); g_csr1[p] = s1[i]; }
}

// ---------------- vectorized input transpose (swizzled smem) ----------------
__global__ void __launch_bounds__(256) k_transpose(const float* __restrict__ inf) {
    __shared__ float4 sm4[64 * 33];
    const float* sm = (const float*)sm4;
    int fi0 = blockIdx.y * 64;
    int n0  = blockIdx.x * 128;
    int tid = threadIdx.x;

    #pragma unroll
    for (int i = 0; i < 8; i++) {
        int idx = i * 256 + tid;
        int f = idx >> 5;
        int v = idx & 31;
        int n = n0 + v * 4;
        if (n < NSRC0) {
            float4 x = *(const float4*)(inf + (size_t)(fi0 + f) * NSRC0 + n);
            sm4[f * 33 + (v ^ (f >> 3))] = x;
        }
    }
    __syncthreads();

    int a  = fi0 >> 8;
    int h0 = (fi0 & 255) >> 1;
    #pragma unroll
    for (int i = 0; i < 8; i++) {
        int idx = i * 256 + tid;
        int ln = idx >> 4;
        int rest = idx & 15;
        int c = rest >> 3;
        int q = rest & 7;
        int n = n0 + ln;
        if (n < NSRC0) {
            int col = (ln >> 2) ^ q;
            int el  = ln & 3;
            float4 o;
            o.x = sm[((8 * q + 0 + c) * 33 + col) * 4 + el];
            o.y = sm[((8 * q + 2 + c) * 33 + col) * 4 + el];
            o.z = sm[((8 * q + 4 + c) * 33 + col) * 4 + el];
            o.w = sm[((8 * q + 6 + c) * 33 + col) * 4 + el];
            *(float4*)(g_X + (size_t)n * FEAT + a * 256 + c * 128 + h0 + q * 4) = o;
        }
    }
}

// ---------------- aggregation: 2 warps per dst (feature-split), 256 feats/warp ----------------
__global__ void k_agg(const int* __restrict__ off, const int* __restrict__ csr,
                      const float* __restrict__ feat, const float* __restrict__ ns,
                      float* __restrict__ out, int ndst) {
    int gw = (blockIdx.x * blockDim.x + threadIdx.x) >> 5;
    int node = gw >> 1;
    int half = gw & 1;
    int lane = threadIdx.x & 31;
    if (node >= ndst) return;
    int beg = off[node], end = off[node + 1];
    const float4* base = (const float4*)feat + half * 64 + lane;
    float4 a0 = make_float4(0.f, 0.f, 0.f, 0.f), a1 = a0;
    int e = beg;
    for (; e + 1 < end; e += 2) {
        int sA = csr[e], sB = csr[e + 1];
        float wA = ns ? ns[sA] : 1.f;
        float wB = ns ? ns[sB] : 1.f;
        const float4* pA = base + (size_t)sA * 128;
        const float4* pB = base + (size_t)sB * 128;
        float4 v0 = pA[0], v1 = pA[32];
        float4 u0 = pB[0], u1 = pB[32];
        a0.x += wA * v0.x + wB * u0.x; a0.y += wA * v0.y + wB * u0.y;
        a0.z += wA * v0.z + wB * u0.z; a0.w += wA * v0.w + wB * u0.w;
        a1.x += wA * v1.x + wB * u1.x; a1.y += wA * v1.y + wB * u1.y;
        a1.z += wA * v1.z + wB * u1.z; a1.w += wA * v1.w + wB * u1.w;
    }
    if (e < end) {
        int sA = csr[e];
        float wA = ns ? ns[sA] : 1.f;
        const float4* pA = base + (size_t)sA * 128;
        float4 v0 = pA[0], v1 = pA[32];
        a0.x += wA * v0.x; a0.y += wA * v0.y; a0.z += wA * v0.z; a0.w += wA * v0.w;
        a1.x += wA * v1.x; a1.y += wA * v1.y; a1.z += wA * v1.z; a1.w += wA * v1.w;
    }
    float4* o = (float4*)out + (size_t)node * 128 + half * 64 + lane;
    o[0] = a0; o[32] = a1;
}

// ---------------- persistent GEMM, cp.async double-buffered A tiles ----------------
// smem: bufA[128*SA] | bufB[128*SA] | Ws[128*SA] | bs[128]  (~198 KB)
#define SA 132
__device__ __forceinline__ void issue_tile_cp(float* dst, const float* __restrict__ src, int tid) {
    #pragma unroll 4
    for (int i = tid; i < 4096; i += 256) {
        int r = i >> 5, k4 = i & 31;
        unsigned sa = (unsigned)__cvta_generic_to_shared(dst + r * SA + k4 * 4);
        asm volatile("cp.async.cg.shared.global [%0], [%1], 16;"
                     :: "r"(sa), "l"(src + r * Hd + k4 * 4));
    }
}

__global__ void __launch_bounds__(256, 1)
k_gemm(const float* __restrict__ A, const float* __restrict__ Wm,
       const float* __restrict__ bias, const float* __restrict__ nd,
       const float* __restrict__ s2, float* __restrict__ Crow, float* __restrict__ Ctr,
       int ntiles) {
    extern __shared__ float sh[];
    float* bufs[2] = { sh, sh + 128 * SA };
    float* Ws = sh + 2 * 128 * SA;
    float* bs = sh + 3 * 128 * SA;
    int tid = threadIdx.x;

    // W + bias once per block
    #pragma unroll 4
    for (int i = tid; i < 4096; i += 256) {
        int k = i >> 5, c4 = i & 31;
        *(float4*)(Ws + k * SA + c4 * 4) = *((const float4*)(Wm + k * Hd) + c4);
    }
    if (tid < 128) bs[tid] = bias[tid];

    // prefetch first tile
    int t0 = blockIdx.x;
    if (t0 < ntiles) issue_tile_cp(bufs[0], A + (size_t)t0 * 128 * Hd, tid);
    asm volatile("cp.async.commit_group;" ::: "memory");

    int pb = 0;
    int rowgrp = tid >> 3;
    int colgrp = tid & 7;

    for (int t = t0; t < ntiles; t += gridDim.x) {
        asm volatile("cp.async.wait_group 0;" ::: "memory");
        __syncthreads();                    // cur buf ready; all threads past previous compute
        float* Ash = bufs[pb];
        int tn = t + gridDim.x;
        if (tn < ntiles) issue_tile_cp(bufs[pb ^ 1], A + (size_t)tn * 128 * Hd, tid);
        asm volatile("cp.async.commit_group;" ::: "memory");
        pb ^= 1;

        unsigned long long acc[4][8];
        #pragma unroll
        for (int i = 0; i < 4; i++)
            #pragma unroll
            for (int j = 0; j < 8; j++) acc[i][j] = 0ull;

        #pragma unroll 4
        for (int k = 0; k < 128; k++) {
            unsigned long long ap[4];
            #pragma unroll
            for (int i = 0; i < 4; i++) {
                float av = Ash[(rowgrp * 4 + i) * SA + k];
                asm("mov.b64 %0, {%1, %1};" : "=l"(ap[i]) : "f"(av));
            }
            ulonglong2 wv[4];
            #pragma unroll
            for (int j = 0; j < 4; j++)
                wv[j] = *(const ulonglong2*)(Ws + k * SA + (j * 8 + colgrp) * 4);
            #pragma unroll
            for (int i = 0; i < 4; i++) {
                #pragma unroll
                for (int j = 0; j < 4; j++) {
                    asm("fma.rn.f32x2 %0, %1, %2, %0;" : "+l"(acc[i][2 * j])     : "l"(ap[i]), "l"(wv[j].x));
                    asm("fma.rn.f32x2 %0, %1, %2, %0;" : "+l"(acc[i][2 * j + 1]) : "l"(ap[i]), "l"(wv[j].y));
                }
            }
        }

        int node0 = t * 32;
        size_t row0 = (size_t)t * 128;

        if (Ctr == nullptr) {
            #pragma unroll
            for (int i = 0; i < 4; i++) {
                int r = rowgrp * 4 + i;
                int node = node0 + (r >> 2);
                float scale = nd[node];
                float s2v = s2 ? s2[node] : 1.f;
                size_t grow = row0 + r;
                #pragma unroll
                for (int j = 0; j < 4; j++) {
                    int c4 = j * 8 + colgrp;
                    float4 o;
                    asm("mov.b64 {%0, %1}, %2;" : "=f"(o.x), "=f"(o.y) : "l"(acc[i][2 * j]));
                    asm("mov.b64 {%0, %1}, %2;" : "=f"(o.z), "=f"(o.w) : "l"(acc[i][2 * j + 1]));
                    float4 bb = *(const float4*)(bs + c4 * 4);
                    o.x = fmaxf(o.x * scale + bb.x, 0.f) * s2v;
                    o.y = fmaxf(o.y * scale + bb.y, 0.f) * s2v;
                    o.z = fmaxf(o.z * scale + bb.z, 0.f) * s2v;
                    o.w = fmaxf(o.w * scale + bb.w, 0.f) * s2v;
                    *(float4*)(Crow + grow * Hd + c4 * 4) = o;
                }
            }
        } else {
            __syncthreads();                 // done reading Ash
            float* Fsh = Ash;                // reuse as [512][33]
            #pragma unroll
            for (int i = 0; i < 4; i++) {
                int r = rowgrp * 4 + i;
                int ln = r >> 2, g = r & 3;
                int node = node0 + ln;
                float scale = nd[node];
                #pragma unroll
                for (int j = 0; j < 4; j++) {
                    int c4 = j * 8 + colgrp;
                    float4 o;
                    asm("mov.b64 {%0, %1}, %2;" : "=f"(o.x), "=f"(o.y) : "l"(acc[i][2 * j]));
                    asm("mov.b64 {%0, %1}, %2;" : "=f"(o.z), "=f"(o.w) : "l"(acc[i][2 * j + 1]));
                    float4 bb = *(const float4*)(bs + c4 * 4);
                    int fb = g * 128 + c4 * 4;
                    Fsh[(fb + 0) * 33 + ln] = fmaxf(o.x * scale + bb.x, 0.f);
                    Fsh[(fb + 1) * 33 + ln] = fmaxf(o.y * scale + bb.y, 0.f);
                    Fsh[(fb + 2) * 33 + ln] = fmaxf(o.z * scale + bb.z, 0.f);
                    Fsh[(fb + 3) * 33 + ln] = fmaxf(o.w * scale + bb.w, 0.f);
                }
            }
            __syncthreads();
            int lane = tid & 31;
            for (int f = tid >> 5; f < FEAT; f += 8) {
                int g = f >> 7, h = f & 127;
                int a = g >> 1, c = g & 1;
                int fo = (a * 128 + h) * 2 + c;
                Ctr[(size_t)fo * NDST1 + node0 + lane] = Fsh[f * 33 + lane];
            }
        }
    }
}

// ---------------- launcher (prep chain || transpose; serial layers) ----------------
extern "C" void kernel_launch(void* const* d_in, const int* in_sizes, int n_in,
                              void* d_out, int out_size) {
    const float* in_feat = (const float*)d_in[0];
    const float* W       = (const float*)d_in[1];
    const float* b       = (const float*)d_in[2];
    const int* e0s = (const int*)d_in[3];
    const int* e0d = (const int*)d_in[4];
    const int* e1s = (const int*)d_in[5];
    const int* e1d = (const int*)d_in[6];
    float* out = (float*)d_out;

    void *pX, *pagg0, *ph0, *pagg1, *pcnt;
    void *poff0, *pcsr0, *poff1, *pcsr1;
    void *pns0, *pnd0, *pns1, *pnd1;
    cudaGetSymbolAddress(&pX, g_X);
    cudaGetSymbolAddress(&pagg0, g_agg0);
    cudaGetSymbolAddress(&ph0, g_h0);
    cudaGetSymbolAddress(&pagg1, g_agg1);
    cudaGetSymbolAddress(&pcnt, g_cnt);
    cudaGetSymbolAddress(&poff0, g_off0);
    cudaGetSymbolAddress(&pcsr0, g_csr0);
    cudaGetSymbolAddress(&poff1, g_off1);
    cudaGetSymbolAddress(&pcsr1, g_csr1);
    cudaGetSymbolAddress(&pns0, g_ns0);
    cudaGetSymbolAddress(&pnd0, g_nd0);
    cudaGetSymbolAddress(&pns1, g_ns1);
    cudaGetSymbolAddress(&pnd1, g_nd1);

    int smem_bytes = (3 * 128 * SA + 128) * (int)sizeof(float);
    cudaFuncSetAttribute(k_gemm, cudaFuncAttributeMaxDynamicSharedMemorySize, smem_bytes);

    static cudaStream_t s2 = nullptr;
    static cudaEvent_t evFork = nullptr, evT = nullptr;
    if (!s2) {
        cudaStreamCreateWithFlags(&s2, cudaStreamNonBlocking);
        cudaEventCreateWithFlags(&evFork, cudaEventDisableTiming);
        cudaEventCreateWithFlags(&evT, cudaEventDisableTiming);
    }

    // fork: transpose on s2 (depends only on in_feat; ns0 applied in agg0)
    cudaEventRecord(evFork, 0);
    cudaStreamWaitEvent(s2, evFork, 0);
    {
        dim3 gr((NSRC0 + 127) / 128, FEAT / 64);
        k_transpose<<<gr, 256, 0, s2>>>(in_feat);
    }
    cudaEventRecord(evT, s2);

    // main stream: graph prep chain
    cudaMemsetAsync(pcnt, 0, CNT_TOTAL * sizeof(int));
    k_hist<<<(E0 + 255) / 256, 256>>>(e0s, e0d, e1s, e1d);
    k_prep<<<2 + (NSRC0 + 1023) / 1024, 1024>>>();
    k_fill<<<(E0 + 255) / 256, 256>>>(e0s, e0d, e1s, e1d);

    cudaStreamWaitEvent(0, evT, 0);

    // layer 0: agg(*ns0[src], 2 warps/node) -> persistent GEMM(*nd0 + b, relu, *ns1)
    k_agg<<<NDST0 / 4, 256>>>((const int*)poff0, (const int*)pcsr0,
                              (const float*)pX, (const float*)pns0,
                              (float*)pagg0, NDST0);
    k_gemm<<<148, 256, smem_bytes>>>((const float*)pagg0, W, b,
                                     (const float*)pnd0, (const float*)pns1,
                                     (float*)ph0, nullptr, NDST0 * 4 / 128);

    // layer 1: agg -> GEMM(*nd1 + b, relu) -> transposed out (grid == ntiles)
    k_agg<<<NDST1 / 4, 256>>>((const int*)poff1, (const int*)pcsr1,
                              (const float*)ph0, (const float*)nullptr,
                              (float*)pagg1, NDST1);
    k_gemm<<<NDST1 * 4 / 128, 256, smem_bytes>>>((const float*)pagg1, W, b,
                                                 (const float*)pnd1, (const float*)nullptr,
                                                 nullptr, out, NDST1 * 4 / 128);

    (void)in_sizes; (void)n_in; (void)out_size;
}

// round 15
// speedup vs baseline: 1.2420x; 1.0988x over previous
#include <cuda_runtime.h>
#include <cuda_fp16.h>
#include <cstdint>
#include <cstddef>

#define Hd 128
#define FEAT 512
#define NSRC0 50000
#define NDST0 20000
#define NDST1 4096
#define E0 320000
#define E1 65536

#define OFF_S0 0
#define OFF_D0 (NSRC0)
#define OFF_S1 (NSRC0 + NDST0)
#define OFF_D1 (NSRC0 + 2 * NDST0)
#define CNT_TOTAL (NSRC0 + 2 * NDST0 + NDST1)

// ---------------- scratch (device globals; no allocations) ----------------
__device__ __half g_Xh[(size_t)NSRC0 * FEAT];    // fp16 node-major src features
__device__ float g_agg0[(size_t)NDST0 * FEAT];
__device__ float g_h0[(size_t)NDST0 * FEAT];
__device__ float g_agg1[(size_t)NDST1 * FEAT];

__device__ int g_cnt[CNT_TOTAL];
__device__ float g_ns0[NSRC0];
__device__ float g_nd0[NDST0];
__device__ float g_ns1[NDST0];
__device__ float g_nd1[NDST1];

__device__ int g_off0[NDST0 + 1];
__device__ int g_cur0[NDST0];
__device__ int g_csr0[E0];
__device__ int g_off1[NDST1 + 1];
__device__ int g_cur1[NDST1];
__device__ int g_csr1[E1];

// ---------------- degree histogram (counts zeroed by memsetAsync) ----------------
__global__ void k_hist(const int* __restrict__ s0, const int* __restrict__ d0,
                       const int* __restrict__ s1, const int* __restrict__ d1) {
    int i = blockIdx.x * blockDim.x + threadIdx.x;
    if (i < E0) {
        atomicAdd(&g_cnt[OFF_S0 + s0[i]], 1);
        atomicAdd(&g_cnt[OFF_D0 + d0[i]], 1);
    }
    if (i < E1) {
        atomicAdd(&g_cnt[OFF_S1 + s1[i]], 1);
        atomicAdd(&g_cnt[OFF_D1 + d1[i]], 1);
    }
}

// ---------------- scan (blocks 0,1) + norms (blocks 2+) ----------------
__global__ void __launch_bounds__(1024) k_prep() {
    int bid = blockIdx.x;
    if (bid < 2) {
        const int* cnt; int* off; int* cur; int n;
        if (bid == 0) { cnt = g_cnt + OFF_D0; off = g_off0; cur = g_cur0; n = NDST0; }
        else          { cnt = g_cnt + OFF_D1; off = g_off1; cur = g_cur1; n = NDST1; }
        int t = threadIdx.x;
        int per = (n + 1023) >> 10;
        int base = t * per;
        int s = 0;
        for (int i = 0; i < per; i++)
            if (base + i < n) s += cnt[base + i];
        int lane = t & 31, wid = t >> 5;
        int v = s;
        #pragma unroll
        for (int d = 1; d < 32; d <<= 1) {
            int x = __shfl_up_sync(~0u, v, d);
            if (lane >= d) v += x;
        }
        __shared__ int wsum[32];
        if (lane == 31) wsum[wid] = v;
        __syncthreads();
        if (wid == 0) {
            int wv = wsum[lane];
            #pragma unroll
            for (int d = 1; d < 32; d <<= 1) {
                int x = __shfl_up_sync(~0u, wv, d);
                if (lane >= d) wv += x;
            }
            wsum[lane] = wv;
        }
        __syncthreads();
        int run = v - s + (wid ? wsum[wid - 1] : 0);
        for (int i = 0; i < per; i++) {
            int idx = base + i;
            if (idx < n) { off[idx] = run; cur[idx] = run; run += cnt[idx]; }
        }
        if (t == 1023) off[n] = run;
    } else {
        int i = (bid - 2) * 1024 + threadIdx.x;
        if (i < NSRC0) g_ns0[i] = rsqrtf((float)max(g_cnt[OFF_S0 + i], 1));
        if (i < NDST0) {
            g_nd0[i] = rsqrtf((float)max(g_cnt[OFF_D0 + i], 1));
            g_ns1[i] = rsqrtf((float)max(g_cnt[OFF_S1 + i], 1));
        }
        if (i < NDST1) g_nd1[i] = rsqrtf((float)max(g_cnt[OFF_D1 + i], 1));
    }
}

__global__ void k_fill(const int* __restrict__ s0, const int* __restrict__ d0,
                       const int* __restrict__ s1, const int* __restrict__ d1) {
    int i = blockIdx.x * blockDim.x + threadIdx.x;
    if (i < E0) { int p = atomicAdd(&g_cur0[d0[i]], 1); g_csr0[p] = s0[i]; }
    if (i < E1) { int p = atomicAdd(&g_cur1[d1[i]], 1); g_csr1[p] = s1[i]; }
}

// ---------------- input transpose -> fp16 X (swizzled smem) ----------------
__global__ void __launch_bounds__(256) k_transpose(const float* __restrict__ inf) {
    __shared__ float4 sm4[64 * 33];
    const float* sm = (const float*)sm4;
    int fi0 = blockIdx.y * 64;
    int n0  = blockIdx.x * 128;
    int tid = threadIdx.x;

    #pragma unroll
    for (int i = 0; i < 8; i++) {
        int idx = i * 256 + tid;
        int f = idx >> 5;
        int v = idx & 31;
        int n = n0 + v * 4;
        if (n < NSRC0) {
            float4 x = *(const float4*)(inf + (size_t)(fi0 + f) * NSRC0 + n);
            sm4[f * 33 + (v ^ (f >> 3))] = x;
        }
    }
    __syncthreads();

    int a  = fi0 >> 8;
    int h0 = (fi0 & 255) >> 1;
    #pragma unroll
    for (int i = 0; i < 8; i++) {
        int idx = i * 256 + tid;
        int ln = idx >> 4;
        int rest = idx & 15;
        int c = rest >> 3;
        int q = rest & 7;
        int n = n0 + ln;
        if (n < NSRC0) {
            int col = (ln >> 2) ^ q;
            int el  = ln & 3;
            float4 o;
            o.x = sm[((8 * q + 0 + c) * 33 + col) * 4 + el];
            o.y = sm[((8 * q + 2 + c) * 33 + col) * 4 + el];
            o.z = sm[((8 * q + 4 + c) * 33 + col) * 4 + el];
            o.w = sm[((8 * q + 6 + c) * 33 + col) * 4 + el];
            __half2 p0 = __floats2half2_rn(o.x, o.y);
            __half2 p1 = __floats2half2_rn(o.z, o.w);
            uint2 pk = make_uint2(*(unsigned*)&p0, *(unsigned*)&p1);
            *(uint2*)(g_Xh + (size_t)n * FEAT + a * 256 + c * 128 + h0 + q * 4) = pk;
        }
    }
}

// ---------------- layer-0 aggregation: warp per dst, fp16 rows, fp32 accum ----------------
__global__ void k_agg_h(const int* __restrict__ off, const int* __restrict__ csr,
                        const __half* __restrict__ feat, const float* __restrict__ ns,
                        float* __restrict__ out, int ndst) {
    int w = (blockIdx.x * blockDim.x + threadIdx.x) >> 5;
    int lane = threadIdx.x & 31;
    if (w >= ndst) return;
    int beg = off[w], end = off[w + 1];
    float acc[16];
    #pragma unroll
    for (int i = 0; i < 16; i++) acc[i] = 0.f;

    const uint4* base = (const uint4*)feat + lane;   // uint4 = 8 halves; 64 per row
    int e = beg;
    for (; e + 1 < end; e += 2) {
        int sA = csr[e], sB = csr[e + 1];
        float wA = ns[sA], wB = ns[sB];
        const uint4* pA = base + (size_t)sA * 64;
        const uint4* pB = base + (size_t)sB * 64;
        uint4 qa0 = pA[0], qa1 = pA[32];
        uint4 qb0 = pB[0], qb1 = pB[32];
        const __half2* ha0 = (const __half2*)&qa0;
        const __half2* ha1 = (const __half2*)&qa1;
        const __half2* hb0 = (const __half2*)&qb0;
        const __half2* hb1 = (const __half2*)&qb1;
        #pragma unroll
        for (int j = 0; j < 4; j++) {
            float2 va = __half22float2(ha0[j]);
            float2 vb = __half22float2(hb0[j]);
            acc[2 * j]     += wA * va.x + wB * vb.x;
            acc[2 * j + 1] += wA * va.y + wB * vb.y;
            float2 wa = __half22float2(ha1[j]);
            float2 wb = __half22float2(hb1[j]);
            acc[8 + 2 * j]     += wA * wa.x + wB * wb.x;
            acc[8 + 2 * j + 1] += wA * wa.y + wB * wb.y;
        }
    }
    if (e < end) {
        int sA = csr[e];
        float wA = ns[sA];
        const uint4* pA = base + (size_t)sA * 64;
        uint4 qa0 = pA[0], qa1 = pA[32];
        const __half2* ha0 = (const __half2*)&qa0;
        const __half2* ha1 = (const __half2*)&qa1;
        #pragma unroll
        for (int j = 0; j < 4; j++) {
            float2 va = __half22float2(ha0[j]);
            acc[2 * j]     += wA * va.x;
            acc[2 * j + 1] += wA * va.y;
            float2 wa = __half22float2(ha1[j]);
            acc[8 + 2 * j]     += wA * wa.x;
            acc[8 + 2 * j + 1] += wA * wa.y;
        }
    }
    // lane's features: [lane*8 .. lane*8+7] and [256+lane*8 .. +7]
    float* orow = out + (size_t)w * FEAT;
    *(float4*)(orow + lane * 8)       = make_float4(acc[0], acc[1], acc[2], acc[3]);
    *(float4*)(orow + lane * 8 + 4)   = make_float4(acc[4], acc[5], acc[6], acc[7]);
    *(float4*)(orow + 256 + lane * 8)     = make_float4(acc[8], acc[9], acc[10], acc[11]);
    *(float4*)(orow + 256 + lane * 8 + 4) = make_float4(acc[12], acc[13], acc[14], acc[15]);
}

// ---------------- layer-1 aggregation: 2 warps per dst (feature-split), fp32 ----------------
__global__ void k_agg(const int* __restrict__ off, const int* __restrict__ csr,
                      const float* __restrict__ feat, float* __restrict__ out, int ndst) {
    int gw = (blockIdx.x * blockDim.x + threadIdx.x) >> 5;
    int node = gw >> 1;
    int half = gw & 1;
    int lane = threadIdx.x & 31;
    if (node >= ndst) return;
    int beg = off[node], end = off[node + 1];
    const float4* base = (const float4*)feat + half * 64 + lane;
    float4 a0 = make_float4(0.f, 0.f, 0.f, 0.f), a1 = a0;
    int e = beg;
    for (; e + 1 < end; e += 2) {
        int sA = csr[e], sB = csr[e + 1];
        const float4* pA = base + (size_t)sA * 128;
        const float4* pB = base + (size_t)sB * 128;
        float4 v0 = pA[0], v1 = pA[32];
        float4 u0 = pB[0], u1 = pB[32];
        a0.x += v0.x + u0.x; a0.y += v0.y + u0.y;
        a0.z += v0.z + u0.z; a0.w += v0.w + u0.w;
        a1.x += v1.x + u1.x; a1.y += v1.y + u1.y;
        a1.z += v1.z + u1.z; a1.w += v1.w + u1.w;
    }
    if (e < end) {
        const float4* pA = base + (size_t)csr[e] * 128;
        float4 v0 = pA[0], v1 = pA[32];
        a0.x += v0.x; a0.y += v0.y; a0.z += v0.z; a0.w += v0.w;
        a1.x += v1.x; a1.y += v1.y; a1.z += v1.z; a1.w += v1.w;
    }
    float4* o = (float4*)out + (size_t)node * 128 + half * 64 + lane;
    o[0] = a0; o[32] = a1;
}

// ---------------- persistent GEMM, cp.async double-buffered A tiles ----------------
#define SA 132
__device__ __forceinline__ void issue_tile_cp(float* dst, const float* __restrict__ src, int tid) {
    #pragma unroll 4
    for (int i = tid; i < 4096; i += 256) {
        int r = i >> 5, k4 = i & 31;
        unsigned sa = (unsigned)__cvta_generic_to_shared(dst + r * SA + k4 * 4);
        asm volatile("cp.async.cg.shared.global [%0], [%1], 16;"
                     :: "r"(sa), "l"(src + r * Hd + k4 * 4));
    }
}

__global__ void __launch_bounds__(256, 1)
k_gemm(const float* __restrict__ A, const float* __restrict__ Wm,
       const float* __restrict__ bias, const float* __restrict__ nd,
       const float* __restrict__ s2, float* __restrict__ Crow, float* __restrict__ Ctr,
       int ntiles) {
    extern __shared__ float sh[];
    float* bufs[2] = { sh, sh + 128 * SA };
    float* Ws = sh + 2 * 128 * SA;
    float* bs = sh + 3 * 128 * SA;
    int tid = threadIdx.x;

    #pragma unroll 4
    for (int i = tid; i < 4096; i += 256) {
        int k = i >> 5, c4 = i & 31;
        *(float4*)(Ws + k * SA + c4 * 4) = *((const float4*)(Wm + k * Hd) + c4);
    }
    if (tid < 128) bs[tid] = bias[tid];

    int t0 = blockIdx.x;
    if (t0 < ntiles) issue_tile_cp(bufs[0], A + (size_t)t0 * 128 * Hd, tid);
    asm volatile("cp.async.commit_group;" ::: "memory");

    int pb = 0;
    int rowgrp = tid >> 3;
    int colgrp = tid & 7;

    for (int t = t0; t < ntiles; t += gridDim.x) {
        asm volatile("cp.async.wait_group 0;" ::: "memory");
        __syncthreads();
        float* Ash = bufs[pb];
        int tn = t + gridDim.x;
        if (tn < ntiles) issue_tile_cp(bufs[pb ^ 1], A + (size_t)tn * 128 * Hd, tid);
        asm volatile("cp.async.commit_group;" ::: "memory");
        pb ^= 1;

        unsigned long long acc[4][8];
        #pragma unroll
        for (int i = 0; i < 4; i++)
            #pragma unroll
            for (int j = 0; j < 8; j++) acc[i][j] = 0ull;

        #pragma unroll 4
        for (int k = 0; k < 128; k++) {
            unsigned long long ap[4];
            #pragma unroll
            for (int i = 0; i < 4; i++) {
                float av = Ash[(rowgrp * 4 + i) * SA + k];
                asm("mov.b64 %0, {%1, %1};" : "=l"(ap[i]) : "f"(av));
            }
            ulonglong2 wv[4];
            #pragma unroll
            for (int j = 0; j < 4; j++)
                wv[j] = *(const ulonglong2*)(Ws + k * SA + (j * 8 + colgrp) * 4);
            #pragma unroll
            for (int i = 0; i < 4; i++) {
                #pragma unroll
                for (int j = 0; j < 4; j++) {
                    asm("fma.rn.f32x2 %0, %1, %2, %0;" : "+l"(acc[i][2 * j])     : "l"(ap[i]), "l"(wv[j].x));
                    asm("fma.rn.f32x2 %0, %1, %2, %0;" : "+l"(acc[i][2 * j + 1]) : "l"(ap[i]), "l"(wv[j].y));
                }
            }
        }

        int node0 = t * 32;
        size_t row0 = (size_t)t * 128;

        if (Ctr == nullptr) {
            #pragma unroll
            for (int i = 0; i < 4; i++) {
                int r = rowgrp * 4 + i;
                int node = node0 + (r >> 2);
                float scale = nd[node];
                float s2v = s2 ? s2[node] : 1.f;
                size_t grow = row0 + r;
                #pragma unroll
                for (int j = 0; j < 4; j++) {
                    int c4 = j * 8 + colgrp;
                    float4 o;
                    asm("mov.b64 {%0, %1}, %2;" : "=f"(o.x), "=f"(o.y) : "l"(acc[i][2 * j]));
                    asm("mov.b64 {%0, %1}, %2;" : "=f"(o.z), "=f"(o.w) : "l"(acc[i][2 * j + 1]));
                    float4 bb = *(const float4*)(bs + c4 * 4);
                    o.x = fmaxf(o.x * scale + bb.x, 0.f) * s2v;
                    o.y = fmaxf(o.y * scale + bb.y, 0.f) * s2v;
                    o.z = fmaxf(o.z * scale + bb.z, 0.f) * s2v;
                    o.w = fmaxf(o.w * scale + bb.w, 0.f) * s2v;
                    *(float4*)(Crow + grow * Hd + c4 * 4) = o;
                }
            }
        } else {
            __syncthreads();
            float* Fsh = Ash;
            #pragma unroll
            for (int i = 0; i < 4; i++) {
                int r = rowgrp * 4 + i;
                int ln = r >> 2, g = r & 3;
                int node = node0 + ln;
                float scale = nd[node];
                #pragma unroll
                for (int j = 0; j < 4; j++) {
                    int c4 = j * 8 + colgrp;
                    float4 o;
                    asm("mov.b64 {%0, %1}, %2;" : "=f"(o.x), "=f"(o.y) : "l"(acc[i][2 * j]));
                    asm("mov.b64 {%0, %1}, %2;" : "=f"(o.z), "=f"(o.w) : "l"(acc[i][2 * j + 1]));
                    float4 bb = *(const float4*)(bs + c4 * 4);
                    int fb = g * 128 + c4 * 4;
                    Fsh[(fb + 0) * 33 + ln] = fmaxf(o.x * scale + bb.x, 0.f);
                    Fsh[(fb + 1) * 33 + ln] = fmaxf(o.y * scale + bb.y, 0.f);
                    Fsh[(fb + 2) * 33 + ln] = fmaxf(o.z * scale + bb.z, 0.f);
                    Fsh[(fb + 3) * 33 + ln] = fmaxf(o.w * scale + bb.w, 0.f);
                }
            }
            __syncthreads();
            int lane = tid & 31;
            for (int f = tid >> 5; f < FEAT; f += 8) {
                int g = f >> 7, h = f & 127;
                int a = g >> 1, c = g & 1;
                int fo = (a * 128 + h) * 2 + c;
                Ctr[(size_t)fo * NDST1 + node0 + lane] = Fsh[f * 33 + lane];
            }
        }
    }
}

// ---------------- launcher ----------------
extern "C" void kernel_launch(void* const* d_in, const int* in_sizes, int n_in,
                              void* d_out, int out_size) {
    const float* in_feat = (const float*)d_in[0];
    const float* W       = (const float*)d_in[1];
    const float* b       = (const float*)d_in[2];
    const int* e0s = (const int*)d_in[3];
    const int* e0d = (const int*)d_in[4];
    const int* e1s = (const int*)d_in[5];
    const int* e1d = (const int*)d_in[6];
    float* out = (float*)d_out;

    void *pXh, *pagg0, *ph0, *pagg1, *pcnt;
    void *poff0, *pcsr0, *poff1, *pcsr1;
    void *pns0, *pnd0, *pns1, *pnd1;
    cudaGetSymbolAddress(&pXh, g_Xh);
    cudaGetSymbolAddress(&pagg0, g_agg0);
    cudaGetSymbolAddress(&ph0, g_h0);
    cudaGetSymbolAddress(&pagg1, g_agg1);
    cudaGetSymbolAddress(&pcnt, g_cnt);
    cudaGetSymbolAddress(&poff0, g_off0);
    cudaGetSymbolAddress(&pcsr0, g_csr0);
    cudaGetSymbolAddress(&poff1, g_off1);
    cudaGetSymbolAddress(&pcsr1, g_csr1);
    cudaGetSymbolAddress(&pns0, g_ns0);
    cudaGetSymbolAddress(&pnd0, g_nd0);
    cudaGetSymbolAddress(&pns1, g_ns1);
    cudaGetSymbolAddress(&pnd1, g_nd1);

    int smem_bytes = (3 * 128 * SA + 128) * (int)sizeof(float);
    cudaFuncSetAttribute(k_gemm, cudaFuncAttributeMaxDynamicSharedMemorySize, smem_bytes);

    static cudaStream_t s2 = nullptr;
    static cudaEvent_t evFork = nullptr, evT = nullptr;
    if (!s2) {
        cudaStreamCreateWithFlags(&s2, cudaStreamNonBlocking);
        cudaEventCreateWithFlags(&evFork, cudaEventDisableTiming);
        cudaEventCreateWithFlags(&evT, cudaEventDisableTiming);
    }

    // main stream: graph prep chain (submitted first so ncu's window hits agg/transpose)
    cudaEventRecord(evFork, 0);
    cudaMemsetAsync(pcnt, 0, CNT_TOTAL * sizeof(int));
    k_hist<<<(E0 + 255) / 256, 256>>>(e0s, e0d, e1s, e1d);
    k_prep<<<2 + (NSRC0 + 1023) / 1024, 1024>>>();
    k_fill<<<(E0 + 255) / 256, 256>>>(e0s, e0d, e1s, e1d);

    // transpose on s2: executes from capture start (waits only on evFork)
    cudaStreamWaitEvent(s2, evFork, 0);
    {
        dim3 gr((NSRC0 + 127) / 128, FEAT / 64);
        k_transpose<<<gr, 256, 0, s2>>>(in_feat);
    }
    cudaEventRecord(evT, s2);
    cudaStreamWaitEvent(0, evT, 0);

    // layer 0: fp16 agg(*ns0[src]) -> persistent GEMM(*nd0 + b, relu, *ns1)
    k_agg_h<<<(NDST0 + 7) / 8, 256>>>((const int*)poff0, (const int*)pcsr0,
                                      (const __half*)pXh, (const float*)pns0,
                                      (float*)pagg0, NDST0);
    k_gemm<<<148, 256, smem_bytes>>>((const float*)pagg0, W, b,
                                     (const float*)pnd0, (const float*)pns1,
                                     (float*)ph0, nullptr, NDST0 * 4 / 128);

    // layer 1: fp32 agg -> GEMM(*nd1 + b, relu) -> transposed out
    k_agg<<<NDST1 / 4, 256>>>((const int*)poff1, (const int*)pcsr1,
                              (const float*)ph0, (float*)pagg1, NDST1);
    k_gemm<<<NDST1 * 4 / 128, 256, smem_bytes>>>((const float*)pagg1, W, b,
                                                 (const float*)pnd1, (const float*)nullptr,
                                                 nullptr, out, NDST1 * 4 / 128);

    (void)in_sizes; (void)n_in; (void)out_size;
}

// round 16
// speedup vs baseline: 1.8802x; 1.5139x over previous
#include <cuda_runtime.h>
#include <cuda_fp16.h>
#include <cstdint>
#include <cstddef>

#define Hd 128
#define FEAT 512
#define NSRC0 50000
#define NDST0 20000
#define NDST1 4096
#define E0 320000
#define E1 65536

#define OFF_S0 0
#define OFF_D0 (NSRC0)
#define OFF_S1 (NSRC0 + NDST0)
#define OFF_D1 (NSRC0 + 2 * NDST0)
#define CNT_TOTAL (NSRC0 + 2 * NDST0 + NDST1)

// ---------------- scratch (device globals; no allocations) ----------------
__device__ __half g_Xh[(size_t)NSRC0 * FEAT];     // fp16 node-major src features
__device__ __half g_agg0[(size_t)NDST0 * FEAT];   // fp16 aggregated layer-0 input
__device__ __half g_h0[(size_t)NDST0 * FEAT];     // fp16 layer-0 output * ns1
__device__ __half g_agg1[(size_t)NDST1 * FEAT];   // fp16 aggregated layer-1 input

__device__ int g_cnt[CNT_TOTAL];
__device__ float g_ns0[NSRC0];
__device__ float g_nd0[NDST0];
__device__ float g_ns1[NDST0];
__device__ float g_nd1[NDST1];

__device__ int g_off0[NDST0 + 1];
__device__ int g_cur0[NDST0];
__device__ int g_csr0[E0];
__device__ int g_off1[NDST1 + 1];
__device__ int g_cur1[NDST1];
__device__ int g_csr1[E1];

// ---------------- degree histogram (counts zeroed by memsetAsync) ----------------
__global__ void k_hist(const int* __restrict__ s0, const int* __restrict__ d0,
                       const int* __restrict__ s1, const int* __restrict__ d1) {
    int i = blockIdx.x * blockDim.x + threadIdx.x;
    if (i < E0) {
        atomicAdd(&g_cnt[OFF_S0 + s0[i]], 1);
        atomicAdd(&g_cnt[OFF_D0 + d0[i]], 1);
    }
    if (i < E1) {
        atomicAdd(&g_cnt[OFF_S1 + s1[i]], 1);
        atomicAdd(&g_cnt[OFF_D1 + d1[i]], 1);
    }
}

// ---------------- scan (blocks 0,1) + norms (blocks 2+) ----------------
__global__ void __launch_bounds__(1024) k_prep() {
    int bid = blockIdx.x;
    if (bid < 2) {
        const int* cnt; int* off; int* cur; int n;
        if (bid == 0) { cnt = g_cnt + OFF_D0; off = g_off0; cur = g_cur0; n = NDST0; }
        else          { cnt = g_cnt + OFF_D1; off = g_off1; cur = g_cur1; n = NDST1; }
        int t = threadIdx.x;
        int per = (n + 1023) >> 10;
        int base = t * per;
        int s = 0;
        for (int i = 0; i < per; i++)
            if (base + i < n) s += cnt[base + i];
        int lane = t & 31, wid = t >> 5;
        int v = s;
        #pragma unroll
        for (int d = 1; d < 32; d <<= 1) {
            int x = __shfl_up_sync(~0u, v, d);
            if (lane >= d) v += x;
        }
        __shared__ int wsum[32];
        if (lane == 31) wsum[wid] = v;
        __syncthreads();
        if (wid == 0) {
            int wv = wsum[lane];
            #pragma unroll
            for (int d = 1; d < 32; d <<= 1) {
                int x = __shfl_up_sync(~0u, wv, d);
                if (lane >= d) wv += x;
            }
            wsum[lane] = wv;
        }
        __syncthreads();
        int run = v - s + (wid ? wsum[wid - 1] : 0);
        for (int i = 0; i < per; i++) {
            int idx = base + i;
            if (idx < n) { off[idx] = run; cur[idx] = run; run += cnt[idx]; }
        }
        if (t == 1023) off[n] = run;
    } else {
        int i = (bid - 2) * 1024 + threadIdx.x;
        if (i < NSRC0) g_ns0[i] = rsqrtf((float)max(g_cnt[OFF_S0 + i], 1));
        if (i < NDST0) {
            g_nd0[i] = rsqrtf((float)max(g_cnt[OFF_D0 + i], 1));
            g_ns1[i] = rsqrtf((float)max(g_cnt[OFF_S1 + i], 1));
        }
        if (i < NDST1) g_nd1[i] = rsqrtf((float)max(g_cnt[OFF_D1 + i], 1));
    }
}

__global__ void k_fill(const int* __restrict__ s0, const int* __restrict__ d0,
                       const int* __restrict__ s1, const int* __restrict__ d1) {
    int i = blockIdx.x * blockDim.x + threadIdx.x;
    if (i < E0) { int p = atomicAdd(&g_cur0[d0[i]], 1); g_csr0[p] = s0[i]; }
    if (i < E1) { int p = atomicAdd(&g_cur1[d1[i]], 1); g_csr1[p] = s1[i]; }
}

// ---------------- input transpose -> fp16 X (swizzled smem) ----------------
__global__ void __launch_bounds__(256) k_transpose(const float* __restrict__ inf) {
    __shared__ float4 sm4[64 * 33];
    const float* sm = (const float*)sm4;
    int fi0 = blockIdx.y * 64;
    int n0  = blockIdx.x * 128;
    int tid = threadIdx.x;

    #pragma unroll
    for (int i = 0; i < 8; i++) {
        int idx = i * 256 + tid;
        int f = idx >> 5;
        int v = idx & 31;
        int n = n0 + v * 4;
        if (n < NSRC0) {
            float4 x = *(const float4*)(inf + (size_t)(fi0 + f) * NSRC0 + n);
            sm4[f * 33 + (v ^ (f >> 3))] = x;
        }
    }
    __syncthreads();

    int a  = fi0 >> 8;
    int h0 = (fi0 & 255) >> 1;
    #pragma unroll
    for (int i = 0; i < 8; i++) {
        int idx = i * 256 + tid;
        int ln = idx >> 4;
        int rest = idx & 15;
        int c = rest >> 3;
        int q = rest & 7;
        int n = n0 + ln;
        if (n < NSRC0) {
            int col = (ln >> 2) ^ q;
            int el  = ln & 3;
            float4 o;
            o.x = sm[((8 * q + 0 + c) * 33 + col) * 4 + el];
            o.y = sm[((8 * q + 2 + c) * 33 + col) * 4 + el];
            o.z = sm[((8 * q + 4 + c) * 33 + col) * 4 + el];
            o.w = sm[((8 * q + 6 + c) * 33 + col) * 4 + el];
            __half2 p0 = __floats2half2_rn(o.x, o.y);
            __half2 p1 = __floats2half2_rn(o.z, o.w);
            uint2 pk = make_uint2(*(unsigned*)&p0, *(unsigned*)&p1);
            *(uint2*)(g_Xh + (size_t)n * FEAT + a * 256 + c * 128 + h0 + q * 4) = pk;
        }
    }
}

// ---------------- aggregation: warp per dst, fp16 rows, fp32 accum, fp16 out ----------------
__global__ void k_agg_h(const int* __restrict__ off, const int* __restrict__ csr,
                        const __half* __restrict__ feat, const float* __restrict__ ns,
                        __half* __restrict__ out, int ndst) {
    int w = (blockIdx.x * blockDim.x + threadIdx.x) >> 5;
    int lane = threadIdx.x & 31;
    if (w >= ndst) return;
    int beg = off[w], end = off[w + 1];
    float acc[16];
    #pragma unroll
    for (int i = 0; i < 16; i++) acc[i] = 0.f;

    const uint4* base = (const uint4*)feat + lane;   // uint4 = 8 halves; 64 per row
    int e = beg;
    for (; e + 1 < end; e += 2) {
        int sA = csr[e], sB = csr[e + 1];
        float wA = ns ? ns[sA] : 1.f;
        float wB = ns ? ns[sB] : 1.f;
        const uint4* pA = base + (size_t)sA * 64;
        const uint4* pB = base + (size_t)sB * 64;
        uint4 qa0 = pA[0], qa1 = pA[32];
        uint4 qb0 = pB[0], qb1 = pB[32];
        const __half2* ha0 = (const __half2*)&qa0;
        const __half2* ha1 = (const __half2*)&qa1;
        const __half2* hb0 = (const __half2*)&qb0;
        const __half2* hb1 = (const __half2*)&qb1;
        #pragma unroll
        for (int j = 0; j < 4; j++) {
            float2 va = __half22float2(ha0[j]);
            float2 vb = __half22float2(hb0[j]);
            acc[2 * j]     += wA * va.x + wB * vb.x;
            acc[2 * j + 1] += wA * va.y + wB * vb.y;
            float2 wa = __half22float2(ha1[j]);
            float2 wb = __half22float2(hb1[j]);
            acc[8 + 2 * j]     += wA * wa.x + wB * wb.x;
            acc[8 + 2 * j + 1] += wA * wa.y + wB * wb.y;
        }
    }
    if (e < end) {
        int sA = csr[e];
        float wA = ns ? ns[sA] : 1.f;
        const uint4* pA = base + (size_t)sA * 64;
        uint4 qa0 = pA[0], qa1 = pA[32];
        const __half2* ha0 = (const __half2*)&qa0;
        const __half2* ha1 = (const __half2*)&qa1;
        #pragma unroll
        for (int j = 0; j < 4; j++) {
            float2 va = __half22float2(ha0[j]);
            acc[2 * j]     += wA * va.x;
            acc[2 * j + 1] += wA * va.y;
            float2 wa = __half22float2(ha1[j]);
            acc[8 + 2 * j]     += wA * wa.x;
            acc[8 + 2 * j + 1] += wA * wa.y;
        }
    }
    // pack fp16 and store: features [lane*8..+7] and [256+lane*8..+7]
    __half2 o0 = __floats2half2_rn(acc[0], acc[1]);
    __half2 o1 = __floats2half2_rn(acc[2], acc[3]);
    __half2 o2 = __floats2half2_rn(acc[4], acc[5]);
    __half2 o3 = __floats2half2_rn(acc[6], acc[7]);
    __half2 o4 = __floats2half2_rn(acc[8], acc[9]);
    __half2 o5 = __floats2half2_rn(acc[10], acc[11]);
    __half2 o6 = __floats2half2_rn(acc[12], acc[13]);
    __half2 o7 = __floats2half2_rn(acc[14], acc[15]);
    __half* orow = out + (size_t)w * FEAT;
    *(uint4*)(orow + lane * 8) =
        make_uint4(*(unsigned*)&o0, *(unsigned*)&o1, *(unsigned*)&o2, *(unsigned*)&o3);
    *(uint4*)(orow + 256 + lane * 8) =
        make_uint4(*(unsigned*)&o4, *(unsigned*)&o5, *(unsigned*)&o6, *(unsigned*)&o7);
}

// ---------------- HMMA GEMM: fp16 A/W, fp32 accum, persistent, cp.async A tiles ----------------
// smem: bufA0[128*PAH] | bufA1 | Ws[128*PAH] (all fp16) | bias fp32[128]
#define PAH 136    // halves; 272B pitch -> LDSM conflict-free, 16B-aligned
__device__ __forceinline__ void issue_tile_cp_h(__half* dst, const __half* __restrict__ src, int tid) {
    #pragma unroll 8
    for (int i = tid; i < 2048; i += 256) {
        int r = i >> 4, k8 = i & 15;
        unsigned sa = (unsigned)__cvta_generic_to_shared(dst + r * PAH + k8 * 8);
        asm volatile("cp.async.cg.shared.global [%0], [%1], 16;"
                     :: "r"(sa), "l"(src + r * Hd + k8 * 8));
    }
}

__global__ void __launch_bounds__(256)
k_gemm_h(const __half* __restrict__ A, const float* __restrict__ Wm,
         const float* __restrict__ bias, const float* __restrict__ nd,
         const float* __restrict__ s2, __half* __restrict__ Crow, float* __restrict__ Ctr,
         int ntiles) {
    extern __shared__ __align__(16) char smem_raw[];
    __half* bufs[2] = { (__half*)smem_raw, (__half*)smem_raw + 128 * PAH };
    __half* Ws = (__half*)smem_raw + 2 * 128 * PAH;
    float* bs = (float*)((__half*)smem_raw + 3 * 128 * PAH);
    int tid = threadIdx.x;
    int lane = tid & 31;
    int wid = tid >> 5;
    int wr = wid >> 1;            // 0..3 -> rows wr*32..+31
    int wc = wid & 1;             // 0..1 -> cols wc*64..+63

    // W fp32 -> fp16 smem [k][n] pitch PAH; bias
    #pragma unroll 4
    for (int i = tid; i < 4096; i += 256) {
        int k = i >> 5, c4 = i & 31;
        float4 v = *((const float4*)(Wm + k * Hd) + c4);
        __half2 h0 = __floats2half2_rn(v.x, v.y);
        __half2 h1 = __floats2half2_rn(v.z, v.w);
        *(uint2*)(Ws + k * PAH + c4 * 4) = make_uint2(*(unsigned*)&h0, *(unsigned*)&h1);
    }
    if (tid < 128) bs[tid] = bias[tid];

    int t0 = blockIdx.x;
    if (t0 < ntiles) issue_tile_cp_h(bufs[0], A + (size_t)t0 * 128 * Hd, tid);
    asm volatile("cp.async.commit_group;" ::: "memory");

    int pb = 0;
    for (int t = t0; t < ntiles; t += gridDim.x) {
        asm volatile("cp.async.wait_group 0;" ::: "memory");
        __syncthreads();
        __half* Ash = bufs[pb];
        int tn = t + gridDim.x;
        if (tn < ntiles) issue_tile_cp_h(bufs[pb ^ 1], A + (size_t)tn * 128 * Hd, tid);
        asm volatile("cp.async.commit_group;" ::: "memory");
        pb ^= 1;

        float acc[2][8][4];
        #pragma unroll
        for (int rt = 0; rt < 2; rt++)
            #pragma unroll
            for (int j = 0; j < 8; j++)
                #pragma unroll
                for (int q = 0; q < 4; q++) acc[rt][j][q] = 0.f;

        #pragma unroll
        for (int k0 = 0; k0 < 8; k0++) {
            unsigned a[2][4];
            #pragma unroll
            for (int rt = 0; rt < 2; rt++) {
                int row = wr * 32 + rt * 16 + (lane & 15);
                unsigned ad = (unsigned)__cvta_generic_to_shared(
                    Ash + row * PAH + k0 * 16 + (lane >> 4) * 8);
                asm volatile("ldmatrix.sync.aligned.m8n8.x4.shared.b16 {%0,%1,%2,%3}, [%4];"
                             : "=r"(a[rt][0]), "=r"(a[rt][1]), "=r"(a[rt][2]), "=r"(a[rt][3])
                             : "r"(ad));
            }
            unsigned bf[8][2];
            #pragma unroll
            for (int p = 0; p < 4; p++) {
                int krow = k0 * 16 + (lane & 15);
                int ncol = wc * 64 + p * 16 + (lane >> 4) * 8;
                unsigned ad = (unsigned)__cvta_generic_to_shared(Ws + krow * PAH + ncol);
                asm volatile("ldmatrix.sync.aligned.m8n8.x4.trans.shared.b16 {%0,%1,%2,%3}, [%4];"
                             : "=r"(bf[2 * p][0]), "=r"(bf[2 * p][1]),
                               "=r"(bf[2 * p + 1][0]), "=r"(bf[2 * p + 1][1])
                             : "r"(ad));
            }
            #pragma unroll
            for (int rt = 0; rt < 2; rt++)
                #pragma unroll
                for (int j = 0; j < 8; j++)
                    asm volatile("mma.sync.aligned.m16n8k16.row.col.f32.f16.f16.f32 "
                                 "{%0,%1,%2,%3}, {%4,%5,%6,%7}, {%8,%9}, {%0,%1,%2,%3};"
                                 : "+f"(acc[rt][j][0]), "+f"(acc[rt][j][1]),
                                   "+f"(acc[rt][j][2]), "+f"(acc[rt][j][3])
                                 : "r"(a[rt][0]), "r"(a[rt][1]), "r"(a[rt][2]), "r"(a[rt][3]),
                                   "r"(bf[j][0]), "r"(bf[j][1]));
        }

        int node0 = t * 32;
        size_t row0 = (size_t)t * 128;
        int gid = lane >> 2, tig = lane & 3;

        if (Ctr == nullptr) {
            // fp16 row-major epilogue -> Crow (h0)
            #pragma unroll
            for (int rt = 0; rt < 2; rt++)
                #pragma unroll
                for (int hh = 0; hh < 2; hh++) {
                    int rl = wr * 32 + rt * 16 + gid + hh * 8;
                    int node = node0 + (rl >> 2);
                    float sc = nd[node];
                    float s2v = s2 ? s2[node] : 1.f;
                    #pragma unroll
                    for (int j = 0; j < 8; j++) {
                        int col = wc * 64 + j * 8 + tig * 2;
                        float o0 = fmaxf(acc[rt][j][hh * 2 + 0] * sc + bs[col], 0.f) * s2v;
                        float o1 = fmaxf(acc[rt][j][hh * 2 + 1] * sc + bs[col + 1], 0.f) * s2v;
                        __half2 hv = __floats2half2_rn(o0, o1);
                        *(__half2*)(Crow + (row0 + rl) * Hd + col) = hv;
                    }
                }
        } else {
            // transposed fp32 epilogue -> Ctr (final output). grid==ntiles here, so
            // no next-tile prefetch is in flight; safe to overlay Fsh on both A bufs.
            __syncthreads();
            float* Fsh = (float*)smem_raw;   // [512][33]
            #pragma unroll
            for (int rt = 0; rt < 2; rt++)
                #pragma unroll
                for (int hh = 0; hh < 2; hh++) {
                    int rl = wr * 32 + rt * 16 + gid + hh * 8;
                    int node = node0 + (rl >> 2);
                    int ln = rl >> 2, g = rl & 3;
                    float sc = nd[node];
                    #pragma unroll
                    for (int j = 0; j < 8; j++) {
                        int col = wc * 64 + j * 8 + tig * 2;
                        float o0 = fmaxf(acc[rt][j][hh * 2 + 0] * sc + bs[col], 0.f);
                        float o1 = fmaxf(acc[rt][j][hh * 2 + 1] * sc + bs[col + 1], 0.f);
                        int f0 = g * 128 + col;
                        Fsh[(f0 + 0) * 33 + ln] = o0;
                        Fsh[(f0 + 1) * 33 + ln] = o1;
                    }
                }
            __syncthreads();
            for (int f = tid >> 5; f < FEAT; f += 8) {
                int g = f >> 7, h = f & 127;
                int a2 = g >> 1, c2 = g & 1;
                int fo = (a2 * 128 + h) * 2 + c2;
                Ctr[(size_t)fo * NDST1 + node0 + lane] = Fsh[f * 33 + lane];
            }
        }
    }
}

// ---------------- launcher ----------------
extern "C" void kernel_launch(void* const* d_in, const int* in_sizes, int n_in,
                              void* d_out, int out_size) {
    const float* in_feat = (const float*)d_in[0];
    const float* W       = (const float*)d_in[1];
    const float* b       = (const float*)d_in[2];
    const int* e0s = (const int*)d_in[3];
    const int* e0d = (const int*)d_in[4];
    const int* e1s = (const int*)d_in[5];
    const int* e1d = (const int*)d_in[6];
    float* out = (float*)d_out;

    void *pXh, *pagg0, *ph0, *pagg1, *pcnt;
    void *poff0, *pcsr0, *poff1, *pcsr1;
    void *pns0, *pnd0, *pns1, *pnd1;
    cudaGetSymbolAddress(&pXh, g_Xh);
    cudaGetSymbolAddress(&pagg0, g_agg0);
    cudaGetSymbolAddress(&ph0, g_h0);
    cudaGetSymbolAddress(&pagg1, g_agg1);
    cudaGetSymbolAddress(&pcnt, g_cnt);
    cudaGetSymbolAddress(&poff0, g_off0);
    cudaGetSymbolAddress(&pcsr0, g_csr0);
    cudaGetSymbolAddress(&poff1, g_off1);
    cudaGetSymbolAddress(&pcsr1, g_csr1);
    cudaGetSymbolAddress(&pns0, g_ns0);
    cudaGetSymbolAddress(&pnd0, g_nd0);
    cudaGetSymbolAddress(&pns1, g_ns1);
    cudaGetSymbolAddress(&pnd1, g_nd1);

    int smem_bytes = 3 * 128 * PAH * 2 + 512;    // fp16 bufs + W + fp32 bias
    cudaFuncSetAttribute(k_gemm_h, cudaFuncAttributeMaxDynamicSharedMemorySize, smem_bytes);

    static cudaStream_t s2 = nullptr;
    static cudaEvent_t evFork = nullptr, evT = nullptr;
    if (!s2) {
        cudaStreamCreateWithFlags(&s2, cudaStreamNonBlocking);
        cudaEventCreateWithFlags(&evFork, cudaEventDisableTiming);
        cudaEventCreateWithFlags(&evT, cudaEventDisableTiming);
    }

    // main stream: graph prep chain
    cudaEventRecord(evFork, 0);
    cudaMemsetAsync(pcnt, 0, CNT_TOTAL * sizeof(int));
    k_hist<<<(E0 + 255) / 256, 256>>>(e0s, e0d, e1s, e1d);
    k_prep<<<2 + (NSRC0 + 1023) / 1024, 1024>>>();
    k_fill<<<(E0 + 255) / 256, 256>>>(e0s, e0d, e1s, e1d);

    // transpose on s2 (waits only on capture start)
    cudaStreamWaitEvent(s2, evFork, 0);
    {
        dim3 gr((NSRC0 + 127) / 128, FEAT / 64);
        k_transpose<<<gr, 256, 0, s2>>>(in_feat);
    }
    cudaEventRecord(evT, s2);
    cudaStreamWaitEvent(0, evT, 0);

    // layer 0: fp16 agg(*ns0[src]) -> HMMA GEMM(*nd0 + b, relu, *ns1) -> fp16 h0
    k_agg_h<<<(NDST0 + 7) / 8, 256>>>((const int*)poff0, (const int*)pcsr0,
                                      (const __half*)pXh, (const float*)pns0,
                                      (__half*)pagg0, NDST0);
    k_gemm_h<<<296, 256, smem_bytes>>>((const __half*)pagg0, W, b,
                                       (const float*)pnd0, (const float*)pns1,
                                       (__half*)ph0, nullptr, NDST0 * 4 / 128);

    // layer 1: fp16 agg -> HMMA GEMM(*nd1 + b, relu) -> transposed fp32 out
    k_agg_h<<<(NDST1 + 7) / 8, 256>>>((const int*)poff1, (const int*)pcsr1,
                                      (const __half*)ph0, (const float*)nullptr,
                                      (__half*)pagg1, NDST1);
    k_gemm_h<<<NDST1 * 4 / 128, 256, smem_bytes>>>((const __half*)pagg1, W, b,
                                                   (const float*)pnd1, (const float*)nullptr,
                                                   nullptr, out, NDST1 * 4 / 128);

    (void)in_sizes; (void)n_in; (void)out_size;
}